// round 13
// baseline (speedup 1.0000x reference)
#include <cuda_runtime.h>
#include <cuda_bf16.h>

#define DEV __device__ __forceinline__

// ---- packed 2x fp32 helpers ----
DEV unsigned long long ffma2(unsigned long long a, unsigned long long b, unsigned long long c) {
    unsigned long long d;
    asm("fma.rn.f32x2 %0, %1, %2, %3;" : "=l"(d) : "l"(a), "l"(b), "l"(c));
    return d;
}
DEV unsigned long long pack2(float lo, float hi) {
    unsigned long long r;
    asm("mov.b64 %0, {%1,%2};" : "=l"(r) : "f"(lo), "f"(hi));
    return r;
}
DEV void unpack2(unsigned long long v, float& lo, float& hi) {
    asm("mov.b64 {%0,%1}, %2;" : "=f"(lo), "=f"(hi) : "l"(v));
}
DEV unsigned int bf2(float lo, float hi) {
    unsigned int r;
    asm("cvt.rn.bf16x2.f32 %0, %1, %2;" : "=r"(r) : "f"(hi), "f"(lo));
    return r;
}
DEV unsigned int tf32r(float f) {
    unsigned int r;
    asm("cvt.rna.tf32.f32 %0, %1;" : "=r"(r) : "f"(f));
    return r;
}
DEV float2 bfu2f(unsigned int u) {
    __nv_bfloat162 h = *(__nv_bfloat162*)&u;
    return make_float2(__bfloat162float(h.x), __bfloat162float(h.y));
}

DEV void mma_qk(float* d, const unsigned int* a, unsigned int b) {
    asm("mma.sync.aligned.m16n8k8.row.col.f32.bf16.bf16.f32 "
        "{%0,%1,%2,%3},{%4,%5},{%6},{%7,%7,%7,%7};"
        : "=f"(d[0]), "=f"(d[1]), "=f"(d[2]), "=f"(d[3])
        : "r"(a[0]), "r"(a[1]), "r"(b), "f"(0.f));
}
DEV void mma_pv(float* d, const unsigned int* a, unsigned int b0, unsigned int b1) {
    asm("mma.sync.aligned.m16n8k16.row.col.f32.bf16.bf16.f32 "
        "{%0,%1,%2,%3},{%4,%5,%6,%7},{%8,%9},{%0,%1,%2,%3};"
        : "+f"(d[0]), "+f"(d[1]), "+f"(d[2]), "+f"(d[3])
        : "r"(a[0]), "r"(a[1]), "r"(a[2]), "r"(a[3]), "r"(b0), "r"(b1));
}
DEV void mma_tf32(float* d, unsigned int a0, unsigned int a1, unsigned int a2, unsigned int a3,
                  unsigned int b0, unsigned int b1) {
    asm("mma.sync.aligned.m16n8k8.row.col.f32.tf32.tf32.f32 "
        "{%0,%1,%2,%3},{%4,%5,%6,%7},{%8,%9},{%0,%1,%2,%3};"
        : "+f"(d[0]), "+f"(d[1]), "+f"(d[2]), "+f"(d[3])
        : "r"(a0), "r"(a1), "r"(a2), "r"(a3), "r"(b0), "r"(b1));
}
DEV void ldsm2t(unsigned int& r0, unsigned int& r1, unsigned int addr) {
    asm volatile("ldmatrix.sync.aligned.m8n8.x2.trans.shared.b16 {%0,%1},[%2];"
                 : "=r"(r0), "=r"(r1) : "r"(addr));
}

DEV void cp16(unsigned int dst, const void* src) {
    asm volatile("cp.async.ca.shared.global [%0], [%1], 16;" :: "r"(dst), "l"(src));
}
DEV void cp_commit() { asm volatile("cp.async.commit_group;"); }

#define BB 8
#define CC 64
#define NN 4096
#define OC 128

// ---- scratch ----
__device__ float g_featb[BB * 8 * NN];
__device__ __align__(16) unsigned int   g_featcT[BB * NN * 4];   // [b][n][8 ch] bf16 packed
__device__ __align__(16) __nv_bfloat16  g_featd16[BB * CC * NN]; // [b][c][n] bf16
__device__ __align__(16) __nv_bfloat16 g_x1h[BB * CC * NN];      // hi bf16 of x1
__device__ __align__(16) __nv_bfloat16 g_x1l[BB * CC * NN];      // lo bf16 of x1
__device__ float g_x2[BB * CC * NN];                             // tf32-rounded
__device__ float g_attp[16 * BB * CC * CC];
__device__ __align__(16) __nv_bfloat16 g_atth[BB * CC * CC];
__device__ __align__(16) __nv_bfloat16 g_attl[BB * CC * CC];
__device__ float g_conv[BB * OC * NN];
__device__ float g_bnp[256 * 256];
__device__ unsigned int g_wT[9 * 64 * 128];   // tf32 weights [tap][ic][oc]

// ============================================================
// Kernel 0: one-time weight transpose + tf32 round
// ============================================================
__global__ void k_wt(const float* __restrict__ w)
{
    int idx = blockIdx.x * 256 + threadIdx.x;
    if (idx >= 9 * 64 * 128) return;
    int tap = idx >> 13;
    int r = idx & 8191;
    int ic = r >> 7, oc = r & 127;
    g_wT[idx] = tf32r(w[(oc * 64 + ic) * 9 + tap]);
}

// ============================================================
// Kernel 1: fused 1x1 projections (f32x2), bf16 outputs for PAM
// ============================================================
__global__ void __launch_bounds__(128) k_proj(
    const float* __restrict__ x,
    const float* __restrict__ wb, const float* __restrict__ bb,
    const float* __restrict__ wc, const float* __restrict__ bc,
    const float* __restrict__ wd, const float* __restrict__ bd)
{
    __shared__ __align__(16) float Ws[80 * 64];
    int b = blockIdx.y;
    int n = blockIdx.x * 128 + threadIdx.x;
    for (int idx = threadIdx.x; idx < 80 * 64; idx += 128) {
        float v;
        if (idx < 512)       v = wb[idx];
        else if (idx < 1024) v = wc[idx - 512];
        else                 v = wd[idx - 1024];
        Ws[idx] = v;
    }
    __syncthreads();

    unsigned long long xv2[32];
#pragma unroll
    for (int j = 0; j < 32; j++)
        xv2[j] = pack2(x[(b * 64 + 2 * j) * NN + n], x[(b * 64 + 2 * j + 1) * NN + n]);

    const unsigned long long* Ws2 = (const unsigned long long*)Ws;

#pragma unroll
    for (int o = 0; o < 8; o++) {
        unsigned long long s2 = 0ull;
        const unsigned long long* w = &Ws2[o * 32];
#pragma unroll
        for (int j = 0; j < 32; j++) s2 = ffma2(w[j], xv2[j], s2);
        float lo, hi; unpack2(s2, lo, hi);
        g_featb[(b * 8 + o) * NN + n] = bb[o] + lo + hi;
    }
    {
        float fc[8];
#pragma unroll
        for (int o = 0; o < 8; o++) {
            unsigned long long s2 = 0ull;
            const unsigned long long* w = &Ws2[256 + o * 32];
#pragma unroll
            for (int j = 0; j < 32; j++) s2 = ffma2(w[j], xv2[j], s2);
            float lo, hi; unpack2(s2, lo, hi);
            fc[o] = bc[o] + lo + hi;
        }
        uint4 p;
        p.x = bf2(fc[0], fc[1]); p.y = bf2(fc[2], fc[3]);
        p.z = bf2(fc[4], fc[5]); p.w = bf2(fc[6], fc[7]);
        ((uint4*)g_featcT)[b * NN + n] = p;
    }
    for (int o = 0; o < 64; o++) {
        unsigned long long s2 = 0ull;
        const unsigned long long* w = &Ws2[512 + o * 32];
#pragma unroll
        for (int j = 0; j < 32; j++) s2 = ffma2(w[j], xv2[j], s2);
        float lo, hi; unpack2(s2, lo, hi);
        g_featd16[(b * 64 + o) * NN + n] = __float2bfloat16_rn(bd[o] + lo + hi);
    }
}

// ============================================================
// Kernel 2: PAM flash attention (bf16 mma + cp.async double buffer).
// Epilogue: transpose through smem (reusing Vs) -> coalesced
// uint4 stores of x1 hi/lo.
// ============================================================
struct PamSmem {
    __align__(16) __nv_bfloat16 Ks[2][128][8];
    __align__(16) unsigned int Vs[2][64][68];   // also reused as float Sf[64][133]
};

__global__ void __launch_bounds__(256, 2) k_pam_tc(
    const float* __restrict__ x, const float* __restrict__ alpha)
{
    __shared__ PamSmem sm;

    int b = blockIdx.y, qt = blockIdx.x;
    int tid = threadIdx.x, warp = tid >> 5, lane = tid & 31;
    int n0 = qt * 128;
    int row = warp * 16 + (lane >> 2);
    int qc = 2 * (lane & 3);

    const float* fb = g_featb + b * 8 * NN;
    unsigned int qa[2];
    qa[0] = bf2(fb[qc * NN + n0 + row],     fb[(qc + 1) * NN + n0 + row]);
    qa[1] = bf2(fb[qc * NN + n0 + row + 8], fb[(qc + 1) * NN + n0 + row + 8]);

    float Oacc[32];
#pragma unroll
    for (int i = 0; i < 32; i++) Oacc[i] = 0.f;
    float ssum0 = 0.f, ssum1 = 0.f;

    const __nv_bfloat16* fcT = (const __nv_bfloat16*)g_featcT + (size_t)b * NN * 8;
    const __nv_bfloat16* fd  = g_featd16 + (size_t)b * 64 * NN;

    unsigned int ksBase = (unsigned int)__cvta_generic_to_shared(&sm.Ks[0][0][0]);
    unsigned int vsBase = (unsigned int)__cvta_generic_to_shared(&sm.Vs[0][0][0]);

    auto stage = [&](int buf, int m0) {
        if (tid < 128)
            cp16(ksBase + (buf * 128 + tid) * 16, fcT + (size_t)(m0 + tid) * 8);
#pragma unroll
        for (int j = 0; j < 4; j++) {
            int id = tid + 256 * j;
            int c = id >> 4, ch = id & 15;
            cp16(vsBase + (buf * 64 * 68 + c * 68 + ch * 4) * 4,
                 fd + (size_t)c * NN + m0 + ch * 8);
        }
    };

    stage(0, 0);
    cp_commit();

    for (int tt = 0; tt < 32; tt++) {
        int cur = tt & 1;
        if (tt < 31) {
            stage(cur ^ 1, (tt + 1) * 128);
            cp_commit();
            asm volatile("cp.async.wait_group 1;");
        } else {
            asm volatile("cp.async.wait_group 0;");
        }
        __syncthreads();

#pragma unroll
        for (int half = 0; half < 2; half++) {
            float Cf[8][4];
#pragma unroll
            for (int nt = 0; nt < 8; nt++) {
                unsigned int kb = *(const unsigned int*)&sm.Ks[cur][half * 64 + nt * 8 + (lane >> 2)][qc];
                mma_qk(Cf[nt], qa, kb);
            }
            unsigned int pa[4][4];
#pragma unroll
            for (int kt = 0; kt < 4; kt++) {
                float ea0 = __expf(Cf[2 * kt][0]),     ea1 = __expf(Cf[2 * kt][1]);
                float ea2 = __expf(Cf[2 * kt][2]),     ea3 = __expf(Cf[2 * kt][3]);
                float eb0 = __expf(Cf[2 * kt + 1][0]), eb1 = __expf(Cf[2 * kt + 1][1]);
                float eb2 = __expf(Cf[2 * kt + 1][2]), eb3 = __expf(Cf[2 * kt + 1][3]);
                ssum0 += (ea0 + ea1) + (eb0 + eb1);
                ssum1 += (ea2 + ea3) + (eb2 + eb3);
                pa[kt][0] = bf2(ea0, ea1);
                pa[kt][1] = bf2(ea2, ea3);
                pa[kt][2] = bf2(eb0, eb1);
                pa[kt][3] = bf2(eb2, eb3);
            }
#pragma unroll
            for (int kt = 0; kt < 4; kt++) {
                int kw = (half * 64 + kt * 16 + 2 * (lane & 3)) >> 1;
#pragma unroll
                for (int nt = 0; nt < 8; nt++) {
                    int c = nt * 8 + (lane >> 2);
                    unsigned int b0 = sm.Vs[cur][c][kw];
                    unsigned int b1 = sm.Vs[cur][c][kw + 4];
                    mma_pv(&Oacc[nt * 4], pa[kt], b0, b1);
                }
            }
        }
        __syncthreads();
    }

    ssum0 += __shfl_xor_sync(0xffffffffu, ssum0, 1);
    ssum0 += __shfl_xor_sync(0xffffffffu, ssum0, 2);
    ssum1 += __shfl_xor_sync(0xffffffffu, ssum1, 1);
    ssum1 += __shfl_xor_sync(0xffffffffu, ssum1, 2);
    float inv0 = __fdividef(1.f, ssum0);
    float inv1 = __fdividef(1.f, ssum1);

    // ---- epilogue: scatter alpha*O into smem (reuse Vs), then
    //      coalesced split-store of x1 hi/lo (+x read coalesced) ----
    float al = alpha[0];
    float* Sf = (float*)&sm.Vs[0][0][0];        // [64][133] = 34.05 KB <= 34.8 KB
#pragma unroll
    for (int nt = 0; nt < 8; nt++) {
#pragma unroll
        for (int j = 0; j < 4; j++) {
            int r = row + ((j >= 2) ? 8 : 0);
            int c = nt * 8 + qc + (j & 1);
            float o = Oacc[nt * 4 + j] * ((j >= 2) ? inv1 : inv0);
            Sf[c * 133 + r] = al * o;
        }
    }
    __syncthreads();
#pragma unroll
    for (int it = 0; it < 4; it++) {
        int id = it * 256 + tid;                // 1024 chunks = 64 c x 16 segs
        int c = id & 63, ch = id >> 6;          // ch 0..15
        size_t off = (size_t)(b * 64 + c) * NN + n0 + ch * 8;
        const float* sp = &Sf[c * 133 + ch * 8];
        const float* xp = &x[off];
        unsigned int hw[4], lw[4];
#pragma unroll
        for (int p = 0; p < 4; p++) {
            float v0 = sp[2 * p] + xp[2 * p];
            float v1 = sp[2 * p + 1] + xp[2 * p + 1];
            __nv_bfloat16 h0 = __float2bfloat16_rn(v0);
            __nv_bfloat16 h1 = __float2bfloat16_rn(v1);
            hw[p] = ((unsigned int)*(unsigned short*)&h1 << 16) | *(unsigned short*)&h0;
            float l0 = v0 - __bfloat162float(h0);
            float l1 = v1 - __bfloat162float(h1);
            lw[p] = bf2(l0, l1);
        }
        *(uint4*)&g_x1h[off] = make_uint4(hw[0], hw[1], hw[2], hw[3]);
        *(uint4*)&g_x1l[off] = make_uint4(lw[0], lw[1], lw[2], lw[3]);
    }
}

// ============================================================
// Kernel 3: CAM gram via bf16 hi/lo split tensor cores.
// 16 k-chunks of 256 cols (R8 config: best measured).
// ============================================================
struct GramSmem {
    __align__(16) __nv_bfloat16 H[64][264];
    __align__(16) __nv_bfloat16 L[64][264];
};

__global__ void __launch_bounds__(256) k_gram_tc()
{
    __shared__ GramSmem sm;
    int ck = blockIdx.x, b = blockIdx.y;
    int tid = threadIdx.x, warp = tid >> 5, lane = tid & 31;
    int n0 = ck * 256;

    unsigned int hBase = (unsigned int)__cvta_generic_to_shared(&sm.H[0][0]);
    unsigned int lBase = (unsigned int)__cvta_generic_to_shared(&sm.L[0][0]);
    for (int i = tid; i < 2048; i += 256) {
        int c = i >> 5, seg = i & 31;
        size_t src = (size_t)(b * 64 + c) * NN + n0 + seg * 8;
        cp16(hBase + (c * 264 + seg * 8) * 2, g_x1h + src);
        cp16(lBase + (c * 264 + seg * 8) * 2, g_x1l + src);
    }
    cp_commit();
    asm volatile("cp.async.wait_group 0;");
    __syncthreads();

    int wr = (warp & 3) * 16;
    int wc = (warp >> 2) * 32;
    int row = lane >> 2, t2 = 2 * (lane & 3);

    float acc[4][4];
#pragma unroll
    for (int i = 0; i < 4; i++)
#pragma unroll
        for (int j = 0; j < 4; j++) acc[i][j] = 0.f;

#pragma unroll 4
    for (int ks = 0; ks < 16; ks++) {
        int k0 = ks * 16;
        unsigned int ah[4], al_[4];
        ah[0]  = *(const unsigned int*)&sm.H[wr + row][k0 + t2];
        ah[1]  = *(const unsigned int*)&sm.H[wr + row + 8][k0 + t2];
        ah[2]  = *(const unsigned int*)&sm.H[wr + row][k0 + t2 + 8];
        ah[3]  = *(const unsigned int*)&sm.H[wr + row + 8][k0 + t2 + 8];
        al_[0] = *(const unsigned int*)&sm.L[wr + row][k0 + t2];
        al_[1] = *(const unsigned int*)&sm.L[wr + row + 8][k0 + t2];
        al_[2] = *(const unsigned int*)&sm.L[wr + row][k0 + t2 + 8];
        al_[3] = *(const unsigned int*)&sm.L[wr + row + 8][k0 + t2 + 8];
#pragma unroll
        for (int nt = 0; nt < 4; nt++) {
            int col = wc + nt * 8 + row;
            unsigned int bh0 = *(const unsigned int*)&sm.H[col][k0 + t2];
            unsigned int bh1 = *(const unsigned int*)&sm.H[col][k0 + t2 + 8];
            unsigned int bl0 = *(const unsigned int*)&sm.L[col][k0 + t2];
            unsigned int bl1 = *(const unsigned int*)&sm.L[col][k0 + t2 + 8];
            mma_pv(acc[nt], ah, bh0, bh1);
            mma_pv(acc[nt], ah, bl0, bl1);
            mma_pv(acc[nt], al_, bh0, bh1);
        }
    }

    float* outp = &g_attp[(ck * 8 + b) * 4096];
#pragma unroll
    for (int nt = 0; nt < 4; nt++)
#pragma unroll
        for (int j = 0; j < 4; j++) {
            int c = wr + row + ((j >= 2) ? 8 : 0);
            int d = wc + nt * 8 + t2 + (j & 1);
            outp[c * 64 + d] = acc[nt][j];
        }
}

// ============================================================
// Kernel 4: partial reduce (16 chunks) + CAM softmax; att hi/lo bf16.
// ============================================================
__global__ void k_cam_softmax()
{
    __shared__ float buf[64];
    int rowid = blockIdx.x;
    int b = rowid >> 6, c = rowid & 63;
    int d = threadIdx.x;
    float v = 0.f;
#pragma unroll
    for (int ch = 0; ch < 16; ch++)
        v += g_attp[(ch * 8 + b) * 4096 + c * 64 + d];
    buf[d] = v;
    __syncthreads();
    for (int s = 32; s > 0; s >>= 1) {
        if (d < s) buf[d] = fminf(buf[d], buf[d + s]);
        __syncthreads();
    }
    float mn = buf[0];
    __syncthreads();
    float p = __expf(mn - v);
    buf[d] = p;
    __syncthreads();
    for (int s = 32; s > 0; s >>= 1) {
        if (d < s) buf[d] += buf[d + s];
        __syncthreads();
    }
    float a = p / buf[0];
    __nv_bfloat16 h = __float2bfloat16_rn(a);
    g_atth[rowid * 64 + d] = h;
    g_attl[rowid * 64 + d] = __float2bfloat16_rn(a - __bfloat162float(h));
}

// ============================================================
// Kernel 5: CAM apply via tensor cores (hi/lo split both operands).
// x2 emitted pre-rounded to tf32 (sole consumer is the tf32 conv).
// ============================================================
struct CamSmem {
    __align__(16) __nv_bfloat16 Ah[64][72];
    __align__(16) __nv_bfloat16 Al[64][72];
    __align__(16) __nv_bfloat16 Xh[64][136];
    __align__(16) __nv_bfloat16 Xl[64][136];
};

__global__ void __launch_bounds__(256) k_cam_apply_tc(const float* __restrict__ beta)
{
    __shared__ CamSmem sm;
    int b = blockIdx.y;
    int n0 = blockIdx.x * 128;
    int tid = threadIdx.x, warp = tid >> 5, lane = tid & 31;
    int wm = warp & 3, wn = warp >> 2;
    int row = lane >> 2, t2 = 2 * (lane & 3);

    unsigned int ahB = (unsigned int)__cvta_generic_to_shared(&sm.Ah[0][0]);
    unsigned int alB = (unsigned int)__cvta_generic_to_shared(&sm.Al[0][0]);
    unsigned int xhB = (unsigned int)__cvta_generic_to_shared(&sm.Xh[0][0]);
    unsigned int xlB = (unsigned int)__cvta_generic_to_shared(&sm.Xl[0][0]);

    for (int i = tid; i < 512; i += 256) {
        int c = i >> 3, seg = i & 7;
        cp16(ahB + (c * 72 + seg * 8) * 2, g_atth + b * 4096 + c * 64 + seg * 8);
        cp16(alB + (c * 72 + seg * 8) * 2, g_attl + b * 4096 + c * 64 + seg * 8);
    }
    for (int i = tid; i < 1024; i += 256) {
        int d = i >> 4, seg = i & 15;
        size_t src = (size_t)(b * 64 + d) * NN + n0 + seg * 8;
        cp16(xhB + (d * 136 + seg * 8) * 2, g_x1h + src);
        cp16(xlB + (d * 136 + seg * 8) * 2, g_x1l + src);
    }
    cp_commit();
    asm volatile("cp.async.wait_group 0;");
    __syncthreads();

    float acc[8][4];
#pragma unroll
    for (int i = 0; i < 8; i++)
#pragma unroll
        for (int j = 0; j < 4; j++) acc[i][j] = 0.f;

    int l15 = lane & 15;
#pragma unroll
    for (int ks = 0; ks < 4; ks++) {
        int d0 = ks * 16;
        unsigned int ah[4], al_[4];
        ah[0]  = *(const unsigned int*)&sm.Ah[wm * 16 + row][d0 + t2];
        ah[1]  = *(const unsigned int*)&sm.Ah[wm * 16 + row + 8][d0 + t2];
        ah[2]  = *(const unsigned int*)&sm.Ah[wm * 16 + row][d0 + t2 + 8];
        ah[3]  = *(const unsigned int*)&sm.Ah[wm * 16 + row + 8][d0 + t2 + 8];
        al_[0] = *(const unsigned int*)&sm.Al[wm * 16 + row][d0 + t2];
        al_[1] = *(const unsigned int*)&sm.Al[wm * 16 + row + 8][d0 + t2];
        al_[2] = *(const unsigned int*)&sm.Al[wm * 16 + row][d0 + t2 + 8];
        al_[3] = *(const unsigned int*)&sm.Al[wm * 16 + row + 8][d0 + t2 + 8];
#pragma unroll
        for (int nf = 0; nf < 8; nf++) {
            int nb = wn * 64 + nf * 8;
            unsigned int bh0, bh1, bl0, bl1;
            ldsm2t(bh0, bh1, xhB + ((d0 + l15) * 136 + nb) * 2);
            ldsm2t(bl0, bl1, xlB + ((d0 + l15) * 136 + nb) * 2);
            mma_pv(acc[nf], ah, bh0, bh1);
            mma_pv(acc[nf], ah, bl0, bl1);
            mma_pv(acc[nf], al_, bh0, bh1);
        }
    }

    float be = beta[0];
#pragma unroll
    for (int nf = 0; nf < 8; nf++) {
#pragma unroll
        for (int jh = 0; jh < 2; jh++) {
            int c = wm * 16 + row + jh * 8;
            int nl = wn * 64 + nf * 8 + t2;
            float2 xh = bfu2f(*(const unsigned int*)&sm.Xh[c][nl]);
            float2 xl = bfu2f(*(const unsigned int*)&sm.Xl[c][nl]);
            float2 o;
            o.x = __uint_as_float(tf32r(be * acc[nf][jh * 2]     + (xh.x + xl.x)));
            o.y = __uint_as_float(tf32r(be * acc[nf][jh * 2 + 1] + (xh.y + xl.y)));
            *(float2*)&g_x2[(size_t)(b * 64 + c) * NN + n0 + nl] = o;
        }
    }
}

// ============================================================
// Kernel 6: conv3x3 tf32 implicit GEMM (R8 weight restage) +
// raw-copy X staging (x2 pre-rounded) + fused BN partial stats.
// ============================================================
struct ConvSmem {
    unsigned int Xs[32 * 296];
    unsigned int Ws[128 * 36];
};

__global__ void __launch_bounds__(256) k_conv_tc(const float* __restrict__ bias)
{
    __shared__ ConvSmem sm;
    __shared__ float bnS[8][32], bnQ[8][32];

    int y0 = blockIdx.x * 2, b = blockIdx.y;
    int tid = threadIdx.x, warp = tid >> 5, lane = tid & 31;
    int g = lane >> 2, t = lane & 3;
    int ocq = warp & 3, rowsel = warp >> 2;
    int mo = ocq * 32;

    float C[64];
#pragma unroll
    for (int i = 0; i < 64; i++) C[i] = 0.f;

    for (int ich = 0; ich < 2; ich++) {
        __syncthreads();
        for (int idx = tid; idx < 32 * 4 * 66; idx += 256) {
            int ic = idx / 264;
            int r = idx - ic * 264;
            int dy = r / 66, col = r - dy * 66;
            int ih = y0 + dy - 1, ix = col - 1;
            float v = 0.f;
            if (ih >= 0 && ih < 64 && ix >= 0 && ix < 64)
                v = g_x2[((b * 64 + ich * 32 + ic) * NN) + ih * 64 + ix];
            sm.Xs[ic * 296 + dy * 72 + col] = __float_as_uint(v);
        }
        for (int tap = 0; tap < 9; tap++) {
            __syncthreads();
            for (int idx = tid; idx < 4096; idx += 256) {
                int icrel = idx >> 7, oc = idx & 127;
                sm.Ws[oc * 36 + icrel] = g_wT[(tap * 64 + ich * 32 + icrel) * 128 + oc];
            }
            __syncthreads();
            int kh = tap / 3, kw = tap - kh * 3;
            int xoff = (rowsel + kh) * 72 + g + kw;
#pragma unroll
            for (int ks = 0; ks < 4; ks++) {
                int k8 = ks * 8;
                unsigned int a0 = sm.Ws[(mo + g) * 36 + k8 + t];
                unsigned int a1 = sm.Ws[(mo + g + 8) * 36 + k8 + t];
                unsigned int a2 = sm.Ws[(mo + g) * 36 + k8 + t + 4];
                unsigned int a3 = sm.Ws[(mo + g + 8) * 36 + k8 + t + 4];
                unsigned int a4 = sm.Ws[(mo + 16 + g) * 36 + k8 + t];
                unsigned int a5 = sm.Ws[(mo + 16 + g + 8) * 36 + k8 + t];
                unsigned int a6 = sm.Ws[(mo + 16 + g) * 36 + k8 + t + 4];
                unsigned int a7 = sm.Ws[(mo + 16 + g + 8) * 36 + k8 + t + 4];
#pragma unroll
                for (int nf = 0; nf < 8; nf++) {
                    unsigned int b0 = sm.Xs[(k8 + t) * 296 + xoff + nf * 8];
                    unsigned int b1 = sm.Xs[(k8 + t + 4) * 296 + xoff + nf * 8];
                    mma_tf32(&C[nf * 4], a0, a1, a2, a3, b0, b1);
                    mma_tf32(&C[32 + nf * 4], a4, a5, a6, a7, b0, b1);
                }
            }
        }
    }

    int oh = y0 + rowsel;
    float psum[2][2], psq[2][2];
#pragma unroll
    for (int mt = 0; mt < 2; mt++) {
        int oc0 = mo + mt * 16 + g, oc1 = oc0 + 8;
        float bs0 = bias[oc0], bs1 = bias[oc1];
        float* base0 = &g_conv[((b * OC + oc0) * NN) + oh * 64];
        float* base1 = &g_conv[((b * OC + oc1) * NN) + oh * 64];
        float s0 = 0.f, q0 = 0.f, s1 = 0.f, q1 = 0.f;
#pragma unroll
        for (int nf = 0; nf < 8; nf++) {
            int px = nf * 8 + 2 * t;
            float v0 = C[mt * 32 + nf * 4 + 0] + bs0;
            float v1 = C[mt * 32 + nf * 4 + 1] + bs0;
            float v2 = C[mt * 32 + nf * 4 + 2] + bs1;
            float v3 = C[mt * 32 + nf * 4 + 3] + bs1;
            *(float2*)&base0[px] = make_float2(v0, v1);
            *(float2*)&base1[px] = make_float2(v2, v3);
            s0 += v0 + v1; q0 += v0 * v0 + v1 * v1;
            s1 += v2 + v3; q1 += v2 * v2 + v3 * v3;
        }
        psum[mt][0] = s0; psq[mt][0] = q0;
        psum[mt][1] = s1; psq[mt][1] = q1;
    }
#pragma unroll
    for (int mt = 0; mt < 2; mt++)
#pragma unroll
        for (int p = 0; p < 2; p++) {
            psum[mt][p] += __shfl_xor_sync(0xffffffffu, psum[mt][p], 1);
            psum[mt][p] += __shfl_xor_sync(0xffffffffu, psum[mt][p], 2);
            psq[mt][p]  += __shfl_xor_sync(0xffffffffu, psq[mt][p], 1);
            psq[mt][p]  += __shfl_xor_sync(0xffffffffu, psq[mt][p], 2);
        }
    if (t == 0) {
#pragma unroll
        for (int mt = 0; mt < 2; mt++)
#pragma unroll
            for (int p = 0; p < 2; p++) {
                int li = mt * 16 + g + p * 8;
                bnS[warp][li] = psum[mt][p];
                bnQ[warp][li] = psq[mt][p];
            }
    }
    __syncthreads();
    {
        int which = tid >> 7, oc = tid & 127;
        int q = oc >> 5, li = oc & 31;
        float v = which ? (bnQ[q][li] + bnQ[q + 4][li])
                        : (bnS[q][li] + bnS[q + 4][li]);
        g_bnp[(b * 32 + blockIdx.x) * 256 + tid] = v;
    }
}

// ============================================================
// Kernel 7: BN stats (inline reduce) + BN + ReLU + maxpool
// ============================================================
__global__ void k_final(const float* __restrict__ gamma,
                        const float* __restrict__ betaBN,
                        float* __restrict__ out)
{
    __shared__ float s1[256], s2b[256];
    int bc = blockIdx.x;
    int b = bc >> 7, ch = bc & 127;
    int tid = threadIdx.x;

    s1[tid]  = g_bnp[tid * 256 + ch];
    s2b[tid] = g_bnp[tid * 256 + 128 + ch];
    __syncthreads();
    for (int st = 128; st > 0; st >>= 1) {
        if (tid < st) { s1[tid] += s1[tid + st]; s2b[tid] += s2b[tid + st]; }
        __syncthreads();
    }
    float mean = s1[0] * (1.f / 32768.f);
    float var = s2b[0] * (1.f / 32768.f) - mean * mean;
    float istd = rsqrtf(var + 1e-5f);

    float ga = gamma[ch], be = betaBN[ch];
    const float* src = &g_conv[(b * OC + ch) * NN];
    float* dst = &out[(b * OC + ch) * 33 * 32];
    for (int idx = tid; idx < 33 * 32; idx += 256) {
        int ohp = idx >> 5, ow = idx & 31;
        float m = 0.f;
        int ih0 = 2 * ohp - 1;
#pragma unroll
        for (int dy = 0; dy < 2; dy++) {
            int ih = ih0 + dy;
            if (ih < 0 || ih > 63) continue;
#pragma unroll
            for (int dx = 0; dx < 2; dx++) {
                float v = src[ih * 64 + 2 * ow + dx];
                v = (v - mean) * istd * ga + be;
                m = fmaxf(m, v);
            }
        }
        dst[ohp * 32 + ow] = m;
    }
}

// ============================================================
extern "C" void kernel_launch(void* const* d_in, const int* in_sizes, int n_in,
                              void* d_out, int out_size)
{
    const float* x      = (const float*)d_in[0];
    const float* wb     = (const float*)d_in[1];
    const float* bbv    = (const float*)d_in[2];
    const float* wc     = (const float*)d_in[3];
    const float* bcv    = (const float*)d_in[4];
    const float* wd     = (const float*)d_in[5];
    const float* bdv    = (const float*)d_in[6];
    const float* alpha  = (const float*)d_in[7];
    const float* beta   = (const float*)d_in[8];
    const float* convw  = (const float*)d_in[9];
    const float* convb  = (const float*)d_in[10];
    const float* gamma  = (const float*)d_in[11];
    const float* bnbeta = (const float*)d_in[12];
    float* out = (float*)d_out;

    k_wt<<<288, 256>>>(convw);
    k_proj<<<dim3(32, 8), 128>>>(x, wb, bbv, wc, bcv, wd, bdv);
    k_pam_tc<<<dim3(32, 8), 256>>>(x, alpha);
    k_gram_tc<<<dim3(16, 8), 256>>>();
    k_cam_softmax<<<512, 64>>>();
    k_cam_apply_tc<<<dim3(32, 8), 256>>>(beta);
    k_conv_tc<<<dim3(32, 8), 256>>>(convb);
    k_final<<<1024, 256>>>(gamma, bnbeta, out);
}

// round 14
// speedup vs baseline: 1.6055x; 1.6055x over previous
#include <cuda_runtime.h>
#include <cuda_bf16.h>

#define DEV __device__ __forceinline__

// ---- packed 2x fp32 helpers ----
DEV unsigned long long ffma2(unsigned long long a, unsigned long long b, unsigned long long c) {
    unsigned long long d;
    asm("fma.rn.f32x2 %0, %1, %2, %3;" : "=l"(d) : "l"(a), "l"(b), "l"(c));
    return d;
}
DEV unsigned long long pack2(float lo, float hi) {
    unsigned long long r;
    asm("mov.b64 %0, {%1,%2};" : "=l"(r) : "f"(lo), "f"(hi));
    return r;
}
DEV void unpack2(unsigned long long v, float& lo, float& hi) {
    asm("mov.b64 {%0,%1}, %2;" : "=f"(lo), "=f"(hi) : "l"(v));
}
DEV unsigned int bf2(float lo, float hi) {
    unsigned int r;
    asm("cvt.rn.bf16x2.f32 %0, %1, %2;" : "=r"(r) : "f"(hi), "f"(lo));
    return r;
}
DEV unsigned int tf32r(float f) {
    unsigned int r;
    asm("cvt.rna.tf32.f32 %0, %1;" : "=r"(r) : "f"(f));
    return r;
}
DEV float2 bfu2f(unsigned int u) {
    __nv_bfloat162 h = *(__nv_bfloat162*)&u;
    return make_float2(__bfloat162float(h.x), __bfloat162float(h.y));
}

DEV void mma_qk(float* d, const unsigned int* a, unsigned int b) {
    asm("mma.sync.aligned.m16n8k8.row.col.f32.bf16.bf16.f32 "
        "{%0,%1,%2,%3},{%4,%5},{%6},{%7,%7,%7,%7};"
        : "=f"(d[0]), "=f"(d[1]), "=f"(d[2]), "=f"(d[3])
        : "r"(a[0]), "r"(a[1]), "r"(b), "f"(0.f));
}
DEV void mma_pv(float* d, const unsigned int* a, unsigned int b0, unsigned int b1) {
    asm("mma.sync.aligned.m16n8k16.row.col.f32.bf16.bf16.f32 "
        "{%0,%1,%2,%3},{%4,%5,%6,%7},{%8,%9},{%0,%1,%2,%3};"
        : "+f"(d[0]), "+f"(d[1]), "+f"(d[2]), "+f"(d[3])
        : "r"(a[0]), "r"(a[1]), "r"(a[2]), "r"(a[3]), "r"(b0), "r"(b1));
}
DEV void mma_tf32(float* d, unsigned int a0, unsigned int a1, unsigned int a2, unsigned int a3,
                  unsigned int b0, unsigned int b1) {
    asm("mma.sync.aligned.m16n8k8.row.col.f32.tf32.tf32.f32 "
        "{%0,%1,%2,%3},{%4,%5,%6,%7},{%8,%9},{%0,%1,%2,%3};"
        : "+f"(d[0]), "+f"(d[1]), "+f"(d[2]), "+f"(d[3])
        : "r"(a0), "r"(a1), "r"(a2), "r"(a3), "r"(b0), "r"(b1));
}
DEV void ldsm2t(unsigned int& r0, unsigned int& r1, unsigned int addr) {
    asm volatile("ldmatrix.sync.aligned.m8n8.x2.trans.shared.b16 {%0,%1},[%2];"
                 : "=r"(r0), "=r"(r1) : "r"(addr));
}

DEV void cp16(unsigned int dst, const void* src) {
    asm volatile("cp.async.ca.shared.global [%0], [%1], 16;" :: "r"(dst), "l"(src));
}
DEV void cp_commit() { asm volatile("cp.async.commit_group;"); }

#define BB 8
#define CC 64
#define NN 4096
#define OC 128

// ---- scratch ----
__device__ float g_featb[BB * 8 * NN];
__device__ __align__(16) unsigned int   g_featcT[BB * NN * 4];   // [b][n][8 ch] bf16 packed
__device__ __align__(16) __nv_bfloat16  g_featd16[BB * CC * NN]; // [b][c][n] bf16
__device__ __align__(16) __nv_bfloat16 g_x1h[BB * CC * NN];      // hi bf16 of x1
__device__ __align__(16) __nv_bfloat16 g_x1l[BB * CC * NN];      // lo bf16 of x1
__device__ float g_x2[BB * CC * NN];                             // tf32-rounded
__device__ float g_attp[16 * BB * CC * CC];
__device__ __align__(16) __nv_bfloat16 g_atth[BB * CC * CC];
__device__ __align__(16) __nv_bfloat16 g_attl[BB * CC * CC];
__device__ float g_conv[BB * OC * NN];
__device__ float g_bnp[256 * 256];
__device__ unsigned int g_wT[9 * 64 * 128];   // tf32 weights [tap][ic][oc]

// ============================================================
// Kernel 0: one-time weight transpose + tf32 round
// ============================================================
__global__ void k_wt(const float* __restrict__ w)
{
    int idx = blockIdx.x * 256 + threadIdx.x;
    if (idx >= 9 * 64 * 128) return;
    int tap = idx >> 13;
    int r = idx & 8191;
    int ic = r >> 7, oc = r & 127;
    g_wT[idx] = tf32r(w[(oc * 64 + ic) * 9 + tap]);
}

// ============================================================
// Kernel 1: fused 1x1 projections (f32x2), bf16 outputs for PAM
// ============================================================
__global__ void __launch_bounds__(128) k_proj(
    const float* __restrict__ x,
    const float* __restrict__ wb, const float* __restrict__ bb,
    const float* __restrict__ wc, const float* __restrict__ bc,
    const float* __restrict__ wd, const float* __restrict__ bd)
{
    __shared__ __align__(16) float Ws[80 * 64];
    int b = blockIdx.y;
    int n = blockIdx.x * 128 + threadIdx.x;
    for (int idx = threadIdx.x; idx < 80 * 64; idx += 128) {
        float v;
        if (idx < 512)       v = wb[idx];
        else if (idx < 1024) v = wc[idx - 512];
        else                 v = wd[idx - 1024];
        Ws[idx] = v;
    }
    __syncthreads();

    unsigned long long xv2[32];
#pragma unroll
    for (int j = 0; j < 32; j++)
        xv2[j] = pack2(x[(b * 64 + 2 * j) * NN + n], x[(b * 64 + 2 * j + 1) * NN + n]);

    const unsigned long long* Ws2 = (const unsigned long long*)Ws;

#pragma unroll
    for (int o = 0; o < 8; o++) {
        unsigned long long s2 = 0ull;
        const unsigned long long* w = &Ws2[o * 32];
#pragma unroll
        for (int j = 0; j < 32; j++) s2 = ffma2(w[j], xv2[j], s2);
        float lo, hi; unpack2(s2, lo, hi);
        g_featb[(b * 8 + o) * NN + n] = bb[o] + lo + hi;
    }
    {
        float fc[8];
#pragma unroll
        for (int o = 0; o < 8; o++) {
            unsigned long long s2 = 0ull;
            const unsigned long long* w = &Ws2[256 + o * 32];
#pragma unroll
            for (int j = 0; j < 32; j++) s2 = ffma2(w[j], xv2[j], s2);
            float lo, hi; unpack2(s2, lo, hi);
            fc[o] = bc[o] + lo + hi;
        }
        uint4 p;
        p.x = bf2(fc[0], fc[1]); p.y = bf2(fc[2], fc[3]);
        p.z = bf2(fc[4], fc[5]); p.w = bf2(fc[6], fc[7]);
        ((uint4*)g_featcT)[b * NN + n] = p;
    }
    for (int o = 0; o < 64; o++) {
        unsigned long long s2 = 0ull;
        const unsigned long long* w = &Ws2[512 + o * 32];
#pragma unroll
        for (int j = 0; j < 32; j++) s2 = ffma2(w[j], xv2[j], s2);
        float lo, hi; unpack2(s2, lo, hi);
        g_featd16[(b * 64 + o) * NN + n] = __float2bfloat16_rn(bd[o] + lo + hi);
    }
}

// ============================================================
// Kernel 2: PAM flash attention (bf16 mma + cp.async double buffer).
// Epilogue: R8 form (scattered 2B stores) — proven no-spill.
// ============================================================
struct PamSmem {
    __align__(16) __nv_bfloat16 Ks[2][128][8];
    __align__(16) unsigned int Vs[2][64][68];
};

__global__ void __launch_bounds__(256, 2) k_pam_tc(
    const float* __restrict__ x, const float* __restrict__ alpha)
{
    __shared__ PamSmem sm;

    int b = blockIdx.y, qt = blockIdx.x;
    int tid = threadIdx.x, warp = tid >> 5, lane = tid & 31;
    int n0 = qt * 128;
    int row = warp * 16 + (lane >> 2);
    int qc = 2 * (lane & 3);

    const float* fb = g_featb + b * 8 * NN;
    unsigned int qa[2];
    qa[0] = bf2(fb[qc * NN + n0 + row],     fb[(qc + 1) * NN + n0 + row]);
    qa[1] = bf2(fb[qc * NN + n0 + row + 8], fb[(qc + 1) * NN + n0 + row + 8]);

    float Oacc[32];
#pragma unroll
    for (int i = 0; i < 32; i++) Oacc[i] = 0.f;
    float ssum0 = 0.f, ssum1 = 0.f;

    const __nv_bfloat16* fcT = (const __nv_bfloat16*)g_featcT + (size_t)b * NN * 8;
    const __nv_bfloat16* fd  = g_featd16 + (size_t)b * 64 * NN;

    unsigned int ksBase = (unsigned int)__cvta_generic_to_shared(&sm.Ks[0][0][0]);
    unsigned int vsBase = (unsigned int)__cvta_generic_to_shared(&sm.Vs[0][0][0]);

    auto stage = [&](int buf, int m0) {
        if (tid < 128)
            cp16(ksBase + (buf * 128 + tid) * 16, fcT + (size_t)(m0 + tid) * 8);
#pragma unroll
        for (int j = 0; j < 4; j++) {
            int id = tid + 256 * j;
            int c = id >> 4, ch = id & 15;
            cp16(vsBase + (buf * 64 * 68 + c * 68 + ch * 4) * 4,
                 fd + (size_t)c * NN + m0 + ch * 8);
        }
    };

    stage(0, 0);
    cp_commit();

    for (int tt = 0; tt < 32; tt++) {
        int cur = tt & 1;
        if (tt < 31) {
            stage(cur ^ 1, (tt + 1) * 128);
            cp_commit();
            asm volatile("cp.async.wait_group 1;");
        } else {
            asm volatile("cp.async.wait_group 0;");
        }
        __syncthreads();

#pragma unroll
        for (int half = 0; half < 2; half++) {
            float Cf[8][4];
#pragma unroll
            for (int nt = 0; nt < 8; nt++) {
                unsigned int kb = *(const unsigned int*)&sm.Ks[cur][half * 64 + nt * 8 + (lane >> 2)][qc];
                mma_qk(Cf[nt], qa, kb);
            }
            unsigned int pa[4][4];
#pragma unroll
            for (int kt = 0; kt < 4; kt++) {
                float ea0 = __expf(Cf[2 * kt][0]),     ea1 = __expf(Cf[2 * kt][1]);
                float ea2 = __expf(Cf[2 * kt][2]),     ea3 = __expf(Cf[2 * kt][3]);
                float eb0 = __expf(Cf[2 * kt + 1][0]), eb1 = __expf(Cf[2 * kt + 1][1]);
                float eb2 = __expf(Cf[2 * kt + 1][2]), eb3 = __expf(Cf[2 * kt + 1][3]);
                ssum0 += (ea0 + ea1) + (eb0 + eb1);
                ssum1 += (ea2 + ea3) + (eb2 + eb3);
                pa[kt][0] = bf2(ea0, ea1);
                pa[kt][1] = bf2(ea2, ea3);
                pa[kt][2] = bf2(eb0, eb1);
                pa[kt][3] = bf2(eb2, eb3);
            }
#pragma unroll
            for (int kt = 0; kt < 4; kt++) {
                int kw = (half * 64 + kt * 16 + 2 * (lane & 3)) >> 1;
#pragma unroll
                for (int nt = 0; nt < 8; nt++) {
                    int c = nt * 8 + (lane >> 2);
                    unsigned int b0 = sm.Vs[cur][c][kw];
                    unsigned int b1 = sm.Vs[cur][c][kw + 4];
                    mma_pv(&Oacc[nt * 4], pa[kt], b0, b1);
                }
            }
        }
        __syncthreads();
    }

    ssum0 += __shfl_xor_sync(0xffffffffu, ssum0, 1);
    ssum0 += __shfl_xor_sync(0xffffffffu, ssum0, 2);
    ssum1 += __shfl_xor_sync(0xffffffffu, ssum1, 1);
    ssum1 += __shfl_xor_sync(0xffffffffu, ssum1, 2);
    float inv0 = __fdividef(1.f, ssum0);
    float inv1 = __fdividef(1.f, ssum1);

    float al = alpha[0];
#pragma unroll
    for (int nt = 0; nt < 8; nt++) {
#pragma unroll
        for (int j = 0; j < 4; j++) {
            int r = row + ((j >= 2) ? 8 : 0);
            int c = nt * 8 + qc + (j & 1);
            int n = n0 + r;
            float o = Oacc[nt * 4 + j] * ((j >= 2) ? inv1 : inv0);
            float v = al * o + x[(b * 64 + c) * NN + n];
            size_t off = (size_t)(b * 64 + c) * NN + n;
            __nv_bfloat16 h = __float2bfloat16_rn(v);
            g_x1h[off] = h;
            g_x1l[off] = __float2bfloat16_rn(v - __bfloat162float(h));
        }
    }
}

// ============================================================
// Kernel 3: CAM gram via bf16 hi/lo split tensor cores.
// 16 k-chunks of 256 cols (R8 config: best measured).
// ============================================================
struct GramSmem {
    __align__(16) __nv_bfloat16 H[64][264];
    __align__(16) __nv_bfloat16 L[64][264];
};

__global__ void __launch_bounds__(256) k_gram_tc()
{
    __shared__ GramSmem sm;
    int ck = blockIdx.x, b = blockIdx.y;
    int tid = threadIdx.x, warp = tid >> 5, lane = tid & 31;
    int n0 = ck * 256;

    unsigned int hBase = (unsigned int)__cvta_generic_to_shared(&sm.H[0][0]);
    unsigned int lBase = (unsigned int)__cvta_generic_to_shared(&sm.L[0][0]);
    for (int i = tid; i < 2048; i += 256) {
        int c = i >> 5, seg = i & 31;
        size_t src = (size_t)(b * 64 + c) * NN + n0 + seg * 8;
        cp16(hBase + (c * 264 + seg * 8) * 2, g_x1h + src);
        cp16(lBase + (c * 264 + seg * 8) * 2, g_x1l + src);
    }
    cp_commit();
    asm volatile("cp.async.wait_group 0;");
    __syncthreads();

    int wr = (warp & 3) * 16;
    int wc = (warp >> 2) * 32;
    int row = lane >> 2, t2 = 2 * (lane & 3);

    float acc[4][4];
#pragma unroll
    for (int i = 0; i < 4; i++)
#pragma unroll
        for (int j = 0; j < 4; j++) acc[i][j] = 0.f;

#pragma unroll 4
    for (int ks = 0; ks < 16; ks++) {
        int k0 = ks * 16;
        unsigned int ah[4], al_[4];
        ah[0]  = *(const unsigned int*)&sm.H[wr + row][k0 + t2];
        ah[1]  = *(const unsigned int*)&sm.H[wr + row + 8][k0 + t2];
        ah[2]  = *(const unsigned int*)&sm.H[wr + row][k0 + t2 + 8];
        ah[3]  = *(const unsigned int*)&sm.H[wr + row + 8][k0 + t2 + 8];
        al_[0] = *(const unsigned int*)&sm.L[wr + row][k0 + t2];
        al_[1] = *(const unsigned int*)&sm.L[wr + row + 8][k0 + t2];
        al_[2] = *(const unsigned int*)&sm.L[wr + row][k0 + t2 + 8];
        al_[3] = *(const unsigned int*)&sm.L[wr + row + 8][k0 + t2 + 8];
#pragma unroll
        for (int nt = 0; nt < 4; nt++) {
            int col = wc + nt * 8 + row;
            unsigned int bh0 = *(const unsigned int*)&sm.H[col][k0 + t2];
            unsigned int bh1 = *(const unsigned int*)&sm.H[col][k0 + t2 + 8];
            unsigned int bl0 = *(const unsigned int*)&sm.L[col][k0 + t2];
            unsigned int bl1 = *(const unsigned int*)&sm.L[col][k0 + t2 + 8];
            mma_pv(acc[nt], ah, bh0, bh1);
            mma_pv(acc[nt], ah, bl0, bl1);
            mma_pv(acc[nt], al_, bh0, bh1);
        }
    }

    float* outp = &g_attp[(ck * 8 + b) * 4096];
#pragma unroll
    for (int nt = 0; nt < 4; nt++)
#pragma unroll
        for (int j = 0; j < 4; j++) {
            int c = wr + row + ((j >= 2) ? 8 : 0);
            int d = wc + nt * 8 + t2 + (j & 1);
            outp[c * 64 + d] = acc[nt][j];
        }
}

// ============================================================
// Kernel 4: partial reduce (16 chunks) + CAM softmax; att hi/lo bf16.
// ============================================================
__global__ void k_cam_softmax()
{
    __shared__ float buf[64];
    int rowid = blockIdx.x;
    int b = rowid >> 6, c = rowid & 63;
    int d = threadIdx.x;
    float v = 0.f;
#pragma unroll
    for (int ch = 0; ch < 16; ch++)
        v += g_attp[(ch * 8 + b) * 4096 + c * 64 + d];
    buf[d] = v;
    __syncthreads();
    for (int s = 32; s > 0; s >>= 1) {
        if (d < s) buf[d] = fminf(buf[d], buf[d + s]);
        __syncthreads();
    }
    float mn = buf[0];
    __syncthreads();
    float p = __expf(mn - v);
    buf[d] = p;
    __syncthreads();
    for (int s = 32; s > 0; s >>= 1) {
        if (d < s) buf[d] += buf[d + s];
        __syncthreads();
    }
    float a = p / buf[0];
    __nv_bfloat16 h = __float2bfloat16_rn(a);
    g_atth[rowid * 64 + d] = h;
    g_attl[rowid * 64 + d] = __float2bfloat16_rn(a - __bfloat162float(h));
}

// ============================================================
// Kernel 5: CAM apply via tensor cores (hi/lo split both operands).
// x2 emitted pre-rounded to tf32 (sole consumer is the tf32 conv).
// ============================================================
struct CamSmem {
    __align__(16) __nv_bfloat16 Ah[64][72];
    __align__(16) __nv_bfloat16 Al[64][72];
    __align__(16) __nv_bfloat16 Xh[64][136];
    __align__(16) __nv_bfloat16 Xl[64][136];
};

__global__ void __launch_bounds__(256) k_cam_apply_tc(const float* __restrict__ beta)
{
    __shared__ CamSmem sm;
    int b = blockIdx.y;
    int n0 = blockIdx.x * 128;
    int tid = threadIdx.x, warp = tid >> 5, lane = tid & 31;
    int wm = warp & 3, wn = warp >> 2;
    int row = lane >> 2, t2 = 2 * (lane & 3);

    unsigned int ahB = (unsigned int)__cvta_generic_to_shared(&sm.Ah[0][0]);
    unsigned int alB = (unsigned int)__cvta_generic_to_shared(&sm.Al[0][0]);
    unsigned int xhB = (unsigned int)__cvta_generic_to_shared(&sm.Xh[0][0]);
    unsigned int xlB = (unsigned int)__cvta_generic_to_shared(&sm.Xl[0][0]);

    for (int i = tid; i < 512; i += 256) {
        int c = i >> 3, seg = i & 7;
        cp16(ahB + (c * 72 + seg * 8) * 2, g_atth + b * 4096 + c * 64 + seg * 8);
        cp16(alB + (c * 72 + seg * 8) * 2, g_attl + b * 4096 + c * 64 + seg * 8);
    }
    for (int i = tid; i < 1024; i += 256) {
        int d = i >> 4, seg = i & 15;
        size_t src = (size_t)(b * 64 + d) * NN + n0 + seg * 8;
        cp16(xhB + (d * 136 + seg * 8) * 2, g_x1h + src);
        cp16(xlB + (d * 136 + seg * 8) * 2, g_x1l + src);
    }
    cp_commit();
    asm volatile("cp.async.wait_group 0;");
    __syncthreads();

    float acc[8][4];
#pragma unroll
    for (int i = 0; i < 8; i++)
#pragma unroll
        for (int j = 0; j < 4; j++) acc[i][j] = 0.f;

    int l15 = lane & 15;
#pragma unroll
    for (int ks = 0; ks < 4; ks++) {
        int d0 = ks * 16;
        unsigned int ah[4], al_[4];
        ah[0]  = *(const unsigned int*)&sm.Ah[wm * 16 + row][d0 + t2];
        ah[1]  = *(const unsigned int*)&sm.Ah[wm * 16 + row + 8][d0 + t2];
        ah[2]  = *(const unsigned int*)&sm.Ah[wm * 16 + row][d0 + t2 + 8];
        ah[3]  = *(const unsigned int*)&sm.Ah[wm * 16 + row + 8][d0 + t2 + 8];
        al_[0] = *(const unsigned int*)&sm.Al[wm * 16 + row][d0 + t2];
        al_[1] = *(const unsigned int*)&sm.Al[wm * 16 + row + 8][d0 + t2];
        al_[2] = *(const unsigned int*)&sm.Al[wm * 16 + row][d0 + t2 + 8];
        al_[3] = *(const unsigned int*)&sm.Al[wm * 16 + row + 8][d0 + t2 + 8];
#pragma unroll
        for (int nf = 0; nf < 8; nf++) {
            int nb = wn * 64 + nf * 8;
            unsigned int bh0, bh1, bl0, bl1;
            ldsm2t(bh0, bh1, xhB + ((d0 + l15) * 136 + nb) * 2);
            ldsm2t(bl0, bl1, xlB + ((d0 + l15) * 136 + nb) * 2);
            mma_pv(acc[nf], ah, bh0, bh1);
            mma_pv(acc[nf], ah, bl0, bl1);
            mma_pv(acc[nf], al_, bh0, bh1);
        }
    }

    float be = beta[0];
#pragma unroll
    for (int nf = 0; nf < 8; nf++) {
#pragma unroll
        for (int jh = 0; jh < 2; jh++) {
            int c = wm * 16 + row + jh * 8;
            int nl = wn * 64 + nf * 8 + t2;
            float2 xh = bfu2f(*(const unsigned int*)&sm.Xh[c][nl]);
            float2 xl = bfu2f(*(const unsigned int*)&sm.Xl[c][nl]);
            float2 o;
            o.x = __uint_as_float(tf32r(be * acc[nf][jh * 2]     + (xh.x + xl.x)));
            o.y = __uint_as_float(tf32r(be * acc[nf][jh * 2 + 1] + (xh.y + xl.y)));
            *(float2*)&g_x2[(size_t)(b * 64 + c) * NN + n0 + nl] = o;
        }
    }
}

// ============================================================
// Kernel 6: conv3x3 tf32 implicit GEMM (R8 weight restage) +
// raw-copy X staging (x2 pre-rounded) + fused BN partial stats.
// ============================================================
struct ConvSmem {
    unsigned int Xs[32 * 296];
    unsigned int Ws[128 * 36];
};

__global__ void __launch_bounds__(256) k_conv_tc(const float* __restrict__ bias)
{
    __shared__ ConvSmem sm;
    __shared__ float bnS[8][32], bnQ[8][32];

    int y0 = blockIdx.x * 2, b = blockIdx.y;
    int tid = threadIdx.x, warp = tid >> 5, lane = tid & 31;
    int g = lane >> 2, t = lane & 3;
    int ocq = warp & 3, rowsel = warp >> 2;
    int mo = ocq * 32;

    float C[64];
#pragma unroll
    for (int i = 0; i < 64; i++) C[i] = 0.f;

    for (int ich = 0; ich < 2; ich++) {
        __syncthreads();
        for (int idx = tid; idx < 32 * 4 * 66; idx += 256) {
            int ic = idx / 264;
            int r = idx - ic * 264;
            int dy = r / 66, col = r - dy * 66;
            int ih = y0 + dy - 1, ix = col - 1;
            float v = 0.f;
            if (ih >= 0 && ih < 64 && ix >= 0 && ix < 64)
                v = g_x2[((b * 64 + ich * 32 + ic) * NN) + ih * 64 + ix];
            sm.Xs[ic * 296 + dy * 72 + col] = __float_as_uint(v);
        }
        for (int tap = 0; tap < 9; tap++) {
            __syncthreads();
            for (int idx = tid; idx < 4096; idx += 256) {
                int icrel = idx >> 7, oc = idx & 127;
                sm.Ws[oc * 36 + icrel] = g_wT[(tap * 64 + ich * 32 + icrel) * 128 + oc];
            }
            __syncthreads();
            int kh = tap / 3, kw = tap - kh * 3;
            int xoff = (rowsel + kh) * 72 + g + kw;
#pragma unroll
            for (int ks = 0; ks < 4; ks++) {
                int k8 = ks * 8;
                unsigned int a0 = sm.Ws[(mo + g) * 36 + k8 + t];
                unsigned int a1 = sm.Ws[(mo + g + 8) * 36 + k8 + t];
                unsigned int a2 = sm.Ws[(mo + g) * 36 + k8 + t + 4];
                unsigned int a3 = sm.Ws[(mo + g + 8) * 36 + k8 + t + 4];
                unsigned int a4 = sm.Ws[(mo + 16 + g) * 36 + k8 + t];
                unsigned int a5 = sm.Ws[(mo + 16 + g + 8) * 36 + k8 + t];
                unsigned int a6 = sm.Ws[(mo + 16 + g) * 36 + k8 + t + 4];
                unsigned int a7 = sm.Ws[(mo + 16 + g + 8) * 36 + k8 + t + 4];
#pragma unroll
                for (int nf = 0; nf < 8; nf++) {
                    unsigned int b0 = sm.Xs[(k8 + t) * 296 + xoff + nf * 8];
                    unsigned int b1 = sm.Xs[(k8 + t + 4) * 296 + xoff + nf * 8];
                    mma_tf32(&C[nf * 4], a0, a1, a2, a3, b0, b1);
                    mma_tf32(&C[32 + nf * 4], a4, a5, a6, a7, b0, b1);
                }
            }
        }
    }

    int oh = y0 + rowsel;
    float psum[2][2], psq[2][2];
#pragma unroll
    for (int mt = 0; mt < 2; mt++) {
        int oc0 = mo + mt * 16 + g, oc1 = oc0 + 8;
        float bs0 = bias[oc0], bs1 = bias[oc1];
        float* base0 = &g_conv[((b * OC + oc0) * NN) + oh * 64];
        float* base1 = &g_conv[((b * OC + oc1) * NN) + oh * 64];
        float s0 = 0.f, q0 = 0.f, s1 = 0.f, q1 = 0.f;
#pragma unroll
        for (int nf = 0; nf < 8; nf++) {
            int px = nf * 8 + 2 * t;
            float v0 = C[mt * 32 + nf * 4 + 0] + bs0;
            float v1 = C[mt * 32 + nf * 4 + 1] + bs0;
            float v2 = C[mt * 32 + nf * 4 + 2] + bs1;
            float v3 = C[mt * 32 + nf * 4 + 3] + bs1;
            *(float2*)&base0[px] = make_float2(v0, v1);
            *(float2*)&base1[px] = make_float2(v2, v3);
            s0 += v0 + v1; q0 += v0 * v0 + v1 * v1;
            s1 += v2 + v3; q1 += v2 * v2 + v3 * v3;
        }
        psum[mt][0] = s0; psq[mt][0] = q0;
        psum[mt][1] = s1; psq[mt][1] = q1;
    }
#pragma unroll
    for (int mt = 0; mt < 2; mt++)
#pragma unroll
        for (int p = 0; p < 2; p++) {
            psum[mt][p] += __shfl_xor_sync(0xffffffffu, psum[mt][p], 1);
            psum[mt][p] += __shfl_xor_sync(0xffffffffu, psum[mt][p], 2);
            psq[mt][p]  += __shfl_xor_sync(0xffffffffu, psq[mt][p], 1);
            psq[mt][p]  += __shfl_xor_sync(0xffffffffu, psq[mt][p], 2);
        }
    if (t == 0) {
#pragma unroll
        for (int mt = 0; mt < 2; mt++)
#pragma unroll
            for (int p = 0; p < 2; p++) {
                int li = mt * 16 + g + p * 8;
                bnS[warp][li] = psum[mt][p];
                bnQ[warp][li] = psq[mt][p];
            }
    }
    __syncthreads();
    {
        int which = tid >> 7, oc = tid & 127;
        int q = oc >> 5, li = oc & 31;
        float v = which ? (bnQ[q][li] + bnQ[q + 4][li])
                        : (bnS[q][li] + bnS[q + 4][li]);
        g_bnp[(b * 32 + blockIdx.x) * 256 + tid] = v;
    }
}

// ============================================================
// Kernel 7: BN stats (inline reduce) + BN + ReLU + maxpool
// ============================================================
__global__ void k_final(const float* __restrict__ gamma,
                        const float* __restrict__ betaBN,
                        float* __restrict__ out)
{
    __shared__ float s1[256], s2b[256];
    int bc = blockIdx.x;
    int b = bc >> 7, ch = bc & 127;
    int tid = threadIdx.x;

    s1[tid]  = g_bnp[tid * 256 + ch];
    s2b[tid] = g_bnp[tid * 256 + 128 + ch];
    __syncthreads();
    for (int st = 128; st > 0; st >>= 1) {
        if (tid < st) { s1[tid] += s1[tid + st]; s2b[tid] += s2b[tid + st]; }
        __syncthreads();
    }
    float mean = s1[0] * (1.f / 32768.f);
    float var = s2b[0] * (1.f / 32768.f) - mean * mean;
    float istd = rsqrtf(var + 1e-5f);

    float ga = gamma[ch], be = betaBN[ch];
    const float* src = &g_conv[(b * OC + ch) * NN];
    float* dst = &out[(b * OC + ch) * 33 * 32];
    for (int idx = tid; idx < 33 * 32; idx += 256) {
        int ohp = idx >> 5, ow = idx & 31;
        float m = 0.f;
        int ih0 = 2 * ohp - 1;
#pragma unroll
        for (int dy = 0; dy < 2; dy++) {
            int ih = ih0 + dy;
            if (ih < 0 || ih > 63) continue;
#pragma unroll
            for (int dx = 0; dx < 2; dx++) {
                float v = src[ih * 64 + 2 * ow + dx];
                v = (v - mean) * istd * ga + be;
                m = fmaxf(m, v);
            }
        }
        dst[ohp * 32 + ow] = m;
    }
}

// ============================================================
extern "C" void kernel_launch(void* const* d_in, const int* in_sizes, int n_in,
                              void* d_out, int out_size)
{
    const float* x      = (const float*)d_in[0];
    const float* wb     = (const float*)d_in[1];
    const float* bbv    = (const float*)d_in[2];
    const float* wc     = (const float*)d_in[3];
    const float* bcv    = (const float*)d_in[4];
    const float* wd     = (const float*)d_in[5];
    const float* bdv    = (const float*)d_in[6];
    const float* alpha  = (const float*)d_in[7];
    const float* beta   = (const float*)d_in[8];
    const float* convw  = (const float*)d_in[9];
    const float* convb  = (const float*)d_in[10];
    const float* gamma  = (const float*)d_in[11];
    const float* bnbeta = (const float*)d_in[12];
    float* out = (float*)d_out;

    k_wt<<<288, 256>>>(convw);
    k_proj<<<dim3(32, 8), 128>>>(x, wb, bbv, wc, bcv, wd, bdv);
    k_pam_tc<<<dim3(32, 8), 256>>>(x, alpha);
    k_gram_tc<<<dim3(16, 8), 256>>>();
    k_cam_softmax<<<512, 64>>>();
    k_cam_apply_tc<<<dim3(32, 8), 256>>>(beta);
    k_conv_tc<<<dim3(32, 8), 256>>>(convb);
    k_final<<<1024, 256>>>(gamma, bnbeta, out);
}

// round 15
// speedup vs baseline: 1.6237x; 1.0114x over previous
#include <cuda_runtime.h>
#include <cuda_bf16.h>

#define DEV __device__ __forceinline__

// ---- packed 2x fp32 helpers ----
DEV unsigned long long ffma2(unsigned long long a, unsigned long long b, unsigned long long c) {
    unsigned long long d;
    asm("fma.rn.f32x2 %0, %1, %2, %3;" : "=l"(d) : "l"(a), "l"(b), "l"(c));
    return d;
}
DEV unsigned long long pack2(float lo, float hi) {
    unsigned long long r;
    asm("mov.b64 %0, {%1,%2};" : "=l"(r) : "f"(lo), "f"(hi));
    return r;
}
DEV void unpack2(unsigned long long v, float& lo, float& hi) {
    asm("mov.b64 {%0,%1}, %2;" : "=f"(lo), "=f"(hi) : "l"(v));
}
DEV unsigned int bf2(float lo, float hi) {
    unsigned int r;
    asm("cvt.rn.bf16x2.f32 %0, %1, %2;" : "=r"(r) : "f"(hi), "f"(lo));
    return r;
}
DEV unsigned int tf32r(float f) {
    unsigned int r;
    asm("cvt.rna.tf32.f32 %0, %1;" : "=r"(r) : "f"(f));
    return r;
}
DEV float2 bfu2f(unsigned int u) {
    __nv_bfloat162 h = *(__nv_bfloat162*)&u;
    return make_float2(__bfloat162float(h.x), __bfloat162float(h.y));
}
// Schraudolph fast exp: ~1.5% RMS multiplicative error, zero-mean.
// FFMA + F2I instead of MUFU (k_pam is MUFU-throughput-bound).
DEV float fexp(float x) {
    float t = fmaf(x, 12102203.0f, 1064866805.0f);
    return __int_as_float(__float2int_rn(t));
}

DEV void mma_qk(float* d, const unsigned int* a, unsigned int b) {
    asm("mma.sync.aligned.m16n8k8.row.col.f32.bf16.bf16.f32 "
        "{%0,%1,%2,%3},{%4,%5},{%6},{%7,%7,%7,%7};"
        : "=f"(d[0]), "=f"(d[1]), "=f"(d[2]), "=f"(d[3])
        : "r"(a[0]), "r"(a[1]), "r"(b), "f"(0.f));
}
DEV void mma_pv(float* d, const unsigned int* a, unsigned int b0, unsigned int b1) {
    asm("mma.sync.aligned.m16n8k16.row.col.f32.bf16.bf16.f32 "
        "{%0,%1,%2,%3},{%4,%5,%6,%7},{%8,%9},{%0,%1,%2,%3};"
        : "+f"(d[0]), "+f"(d[1]), "+f"(d[2]), "+f"(d[3])
        : "r"(a[0]), "r"(a[1]), "r"(a[2]), "r"(a[3]), "r"(b0), "r"(b1));
}
DEV void mma_tf32(float* d, unsigned int a0, unsigned int a1, unsigned int a2, unsigned int a3,
                  unsigned int b0, unsigned int b1) {
    asm("mma.sync.aligned.m16n8k8.row.col.f32.tf32.tf32.f32 "
        "{%0,%1,%2,%3},{%4,%5,%6,%7},{%8,%9},{%0,%1,%2,%3};"
        : "+f"(d[0]), "+f"(d[1]), "+f"(d[2]), "+f"(d[3])
        : "r"(a0), "r"(a1), "r"(a2), "r"(a3), "r"(b0), "r"(b1));
}
DEV void ldsm2t(unsigned int& r0, unsigned int& r1, unsigned int addr) {
    asm volatile("ldmatrix.sync.aligned.m8n8.x2.trans.shared.b16 {%0,%1},[%2];"
                 : "=r"(r0), "=r"(r1) : "r"(addr));
}

DEV void cp16(unsigned int dst, const void* src) {
    asm volatile("cp.async.ca.shared.global [%0], [%1], 16;" :: "r"(dst), "l"(src));
}
DEV void cp_commit() { asm volatile("cp.async.commit_group;"); }

#define BB 8
#define CC 64
#define NN 4096
#define OC 128

// ---- scratch ----
__device__ float g_featb[BB * 8 * NN];
__device__ __align__(16) unsigned int   g_featcT[BB * NN * 4];   // [b][n][8 ch] bf16 packed
__device__ __align__(16) __nv_bfloat16  g_featd16[BB * CC * NN]; // [b][c][n] bf16
__device__ __align__(16) __nv_bfloat16 g_x1h[BB * CC * NN];      // hi bf16 of x1
__device__ __align__(16) __nv_bfloat16 g_x1l[BB * CC * NN];      // lo bf16 of x1
__device__ float g_x2[BB * CC * NN];                             // tf32-rounded
__device__ float g_attp[16 * BB * CC * CC];
__device__ __align__(16) __nv_bfloat16 g_atth[BB * CC * CC];
__device__ __align__(16) __nv_bfloat16 g_attl[BB * CC * CC];
__device__ float g_conv[BB * OC * NN];
__device__ float g_bnp[256 * 256];
__device__ unsigned int g_wT[9 * 64 * 128];   // tf32 weights [tap][ic][oc]

// ============================================================
// Kernel 0: one-time weight transpose + tf32 round
// ============================================================
__global__ void k_wt(const float* __restrict__ w)
{
    int idx = blockIdx.x * 256 + threadIdx.x;
    if (idx >= 9 * 64 * 128) return;
    int tap = idx >> 13;
    int r = idx & 8191;
    int ic = r >> 7, oc = r & 127;
    g_wT[idx] = tf32r(w[(oc * 64 + ic) * 9 + tap]);
}

// ============================================================
// Kernel 1: fused 1x1 projections (f32x2), bf16 outputs for PAM
// ============================================================
__global__ void __launch_bounds__(128) k_proj(
    const float* __restrict__ x,
    const float* __restrict__ wb, const float* __restrict__ bb,
    const float* __restrict__ wc, const float* __restrict__ bc,
    const float* __restrict__ wd, const float* __restrict__ bd)
{
    __shared__ __align__(16) float Ws[80 * 64];
    int b = blockIdx.y;
    int n = blockIdx.x * 128 + threadIdx.x;
    for (int idx = threadIdx.x; idx < 80 * 64; idx += 128) {
        float v;
        if (idx < 512)       v = wb[idx];
        else if (idx < 1024) v = wc[idx - 512];
        else                 v = wd[idx - 1024];
        Ws[idx] = v;
    }
    __syncthreads();

    unsigned long long xv2[32];
#pragma unroll
    for (int j = 0; j < 32; j++)
        xv2[j] = pack2(x[(b * 64 + 2 * j) * NN + n], x[(b * 64 + 2 * j + 1) * NN + n]);

    const unsigned long long* Ws2 = (const unsigned long long*)Ws;

#pragma unroll
    for (int o = 0; o < 8; o++) {
        unsigned long long s2 = 0ull;
        const unsigned long long* w = &Ws2[o * 32];
#pragma unroll
        for (int j = 0; j < 32; j++) s2 = ffma2(w[j], xv2[j], s2);
        float lo, hi; unpack2(s2, lo, hi);
        g_featb[(b * 8 + o) * NN + n] = bb[o] + lo + hi;
    }
    {
        float fc[8];
#pragma unroll
        for (int o = 0; o < 8; o++) {
            unsigned long long s2 = 0ull;
            const unsigned long long* w = &Ws2[256 + o * 32];
#pragma unroll
            for (int j = 0; j < 32; j++) s2 = ffma2(w[j], xv2[j], s2);
            float lo, hi; unpack2(s2, lo, hi);
            fc[o] = bc[o] + lo + hi;
        }
        uint4 p;
        p.x = bf2(fc[0], fc[1]); p.y = bf2(fc[2], fc[3]);
        p.z = bf2(fc[4], fc[5]); p.w = bf2(fc[6], fc[7]);
        ((uint4*)g_featcT)[b * NN + n] = p;
    }
    for (int o = 0; o < 64; o++) {
        unsigned long long s2 = 0ull;
        const unsigned long long* w = &Ws2[512 + o * 32];
#pragma unroll
        for (int j = 0; j < 32; j++) s2 = ffma2(w[j], xv2[j], s2);
        float lo, hi; unpack2(s2, lo, hi);
        g_featd16[(b * 64 + o) * NN + n] = __float2bfloat16_rn(bd[o] + lo + hi);
    }
}

// ============================================================
// Kernel 2: PAM flash attention (bf16 mma + cp.async double buffer).
// exp via Schraudolph bit-hack (FFMA+F2I) — removes MUFU bottleneck.
// ============================================================
struct PamSmem {
    __align__(16) __nv_bfloat16 Ks[2][128][8];
    __align__(16) unsigned int Vs[2][64][68];
};

__global__ void __launch_bounds__(256, 2) k_pam_tc(
    const float* __restrict__ x, const float* __restrict__ alpha)
{
    __shared__ PamSmem sm;

    int b = blockIdx.y, qt = blockIdx.x;
    int tid = threadIdx.x, warp = tid >> 5, lane = tid & 31;
    int n0 = qt * 128;
    int row = warp * 16 + (lane >> 2);
    int qc = 2 * (lane & 3);

    const float* fb = g_featb + b * 8 * NN;
    unsigned int qa[2];
    qa[0] = bf2(fb[qc * NN + n0 + row],     fb[(qc + 1) * NN + n0 + row]);
    qa[1] = bf2(fb[qc * NN + n0 + row + 8], fb[(qc + 1) * NN + n0 + row + 8]);

    float Oacc[32];
#pragma unroll
    for (int i = 0; i < 32; i++) Oacc[i] = 0.f;
    float ssum0 = 0.f, ssum1 = 0.f;

    const __nv_bfloat16* fcT = (const __nv_bfloat16*)g_featcT + (size_t)b * NN * 8;
    const __nv_bfloat16* fd  = g_featd16 + (size_t)b * 64 * NN;

    unsigned int ksBase = (unsigned int)__cvta_generic_to_shared(&sm.Ks[0][0][0]);
    unsigned int vsBase = (unsigned int)__cvta_generic_to_shared(&sm.Vs[0][0][0]);

    auto stage = [&](int buf, int m0) {
        if (tid < 128)
            cp16(ksBase + (buf * 128 + tid) * 16, fcT + (size_t)(m0 + tid) * 8);
#pragma unroll
        for (int j = 0; j < 4; j++) {
            int id = tid + 256 * j;
            int c = id >> 4, ch = id & 15;
            cp16(vsBase + (buf * 64 * 68 + c * 68 + ch * 4) * 4,
                 fd + (size_t)c * NN + m0 + ch * 8);
        }
    };

    stage(0, 0);
    cp_commit();

    for (int tt = 0; tt < 32; tt++) {
        int cur = tt & 1;
        if (tt < 31) {
            stage(cur ^ 1, (tt + 1) * 128);
            cp_commit();
            asm volatile("cp.async.wait_group 1;");
        } else {
            asm volatile("cp.async.wait_group 0;");
        }
        __syncthreads();

#pragma unroll
        for (int half = 0; half < 2; half++) {
            float Cf[8][4];
#pragma unroll
            for (int nt = 0; nt < 8; nt++) {
                unsigned int kb = *(const unsigned int*)&sm.Ks[cur][half * 64 + nt * 8 + (lane >> 2)][qc];
                mma_qk(Cf[nt], qa, kb);
            }
            unsigned int pa[4][4];
#pragma unroll
            for (int kt = 0; kt < 4; kt++) {
                float ea0 = fexp(Cf[2 * kt][0]),     ea1 = fexp(Cf[2 * kt][1]);
                float ea2 = fexp(Cf[2 * kt][2]),     ea3 = fexp(Cf[2 * kt][3]);
                float eb0 = fexp(Cf[2 * kt + 1][0]), eb1 = fexp(Cf[2 * kt + 1][1]);
                float eb2 = fexp(Cf[2 * kt + 1][2]), eb3 = fexp(Cf[2 * kt + 1][3]);
                ssum0 += (ea0 + ea1) + (eb0 + eb1);
                ssum1 += (ea2 + ea3) + (eb2 + eb3);
                pa[kt][0] = bf2(ea0, ea1);
                pa[kt][1] = bf2(ea2, ea3);
                pa[kt][2] = bf2(eb0, eb1);
                pa[kt][3] = bf2(eb2, eb3);
            }
#pragma unroll
            for (int kt = 0; kt < 4; kt++) {
                int kw = (half * 64 + kt * 16 + 2 * (lane & 3)) >> 1;
#pragma unroll
                for (int nt = 0; nt < 8; nt++) {
                    int c = nt * 8 + (lane >> 2);
                    unsigned int b0 = sm.Vs[cur][c][kw];
                    unsigned int b1 = sm.Vs[cur][c][kw + 4];
                    mma_pv(&Oacc[nt * 4], pa[kt], b0, b1);
                }
            }
        }
        __syncthreads();
    }

    ssum0 += __shfl_xor_sync(0xffffffffu, ssum0, 1);
    ssum0 += __shfl_xor_sync(0xffffffffu, ssum0, 2);
    ssum1 += __shfl_xor_sync(0xffffffffu, ssum1, 1);
    ssum1 += __shfl_xor_sync(0xffffffffu, ssum1, 2);
    float inv0 = __fdividef(1.f, ssum0);
    float inv1 = __fdividef(1.f, ssum1);

    float al = alpha[0];
#pragma unroll
    for (int nt = 0; nt < 8; nt++) {
#pragma unroll
        for (int j = 0; j < 4; j++) {
            int r = row + ((j >= 2) ? 8 : 0);
            int c = nt * 8 + qc + (j & 1);
            int n = n0 + r;
            float o = Oacc[nt * 4 + j] * ((j >= 2) ? inv1 : inv0);
            float v = al * o + x[(b * 64 + c) * NN + n];
            size_t off = (size_t)(b * 64 + c) * NN + n;
            __nv_bfloat16 h = __float2bfloat16_rn(v);
            g_x1h[off] = h;
            g_x1l[off] = __float2bfloat16_rn(v - __bfloat162float(h));
        }
    }
}

// ============================================================
// Kernel 3: CAM gram via bf16 hi/lo split tensor cores.
// ============================================================
struct GramSmem {
    __align__(16) __nv_bfloat16 H[64][264];
    __align__(16) __nv_bfloat16 L[64][264];
};

__global__ void __launch_bounds__(256) k_gram_tc()
{
    __shared__ GramSmem sm;
    int ck = blockIdx.x, b = blockIdx.y;
    int tid = threadIdx.x, warp = tid >> 5, lane = tid & 31;
    int n0 = ck * 256;

    unsigned int hBase = (unsigned int)__cvta_generic_to_shared(&sm.H[0][0]);
    unsigned int lBase = (unsigned int)__cvta_generic_to_shared(&sm.L[0][0]);
    for (int i = tid; i < 2048; i += 256) {
        int c = i >> 5, seg = i & 31;
        size_t src = (size_t)(b * 64 + c) * NN + n0 + seg * 8;
        cp16(hBase + (c * 264 + seg * 8) * 2, g_x1h + src);
        cp16(lBase + (c * 264 + seg * 8) * 2, g_x1l + src);
    }
    cp_commit();
    asm volatile("cp.async.wait_group 0;");
    __syncthreads();

    int wr = (warp & 3) * 16;
    int wc = (warp >> 2) * 32;
    int row = lane >> 2, t2 = 2 * (lane & 3);

    float acc[4][4];
#pragma unroll
    for (int i = 0; i < 4; i++)
#pragma unroll
        for (int j = 0; j < 4; j++) acc[i][j] = 0.f;

#pragma unroll 4
    for (int ks = 0; ks < 16; ks++) {
        int k0 = ks * 16;
        unsigned int ah[4], al_[4];
        ah[0]  = *(const unsigned int*)&sm.H[wr + row][k0 + t2];
        ah[1]  = *(const unsigned int*)&sm.H[wr + row + 8][k0 + t2];
        ah[2]  = *(const unsigned int*)&sm.H[wr + row][k0 + t2 + 8];
        ah[3]  = *(const unsigned int*)&sm.H[wr + row + 8][k0 + t2 + 8];
        al_[0] = *(const unsigned int*)&sm.L[wr + row][k0 + t2];
        al_[1] = *(const unsigned int*)&sm.L[wr + row + 8][k0 + t2];
        al_[2] = *(const unsigned int*)&sm.L[wr + row][k0 + t2 + 8];
        al_[3] = *(const unsigned int*)&sm.L[wr + row + 8][k0 + t2 + 8];
#pragma unroll
        for (int nt = 0; nt < 4; nt++) {
            int col = wc + nt * 8 + row;
            unsigned int bh0 = *(const unsigned int*)&sm.H[col][k0 + t2];
            unsigned int bh1 = *(const unsigned int*)&sm.H[col][k0 + t2 + 8];
            unsigned int bl0 = *(const unsigned int*)&sm.L[col][k0 + t2];
            unsigned int bl1 = *(const unsigned int*)&sm.L[col][k0 + t2 + 8];
            mma_pv(acc[nt], ah, bh0, bh1);
            mma_pv(acc[nt], ah, bl0, bl1);
            mma_pv(acc[nt], al_, bh0, bh1);
        }
    }

    float* outp = &g_attp[(ck * 8 + b) * 4096];
#pragma unroll
    for (int nt = 0; nt < 4; nt++)
#pragma unroll
        for (int j = 0; j < 4; j++) {
            int c = wr + row + ((j >= 2) ? 8 : 0);
            int d = wc + nt * 8 + t2 + (j & 1);
            outp[c * 64 + d] = acc[nt][j];
        }
}

// ============================================================
// Kernel 4: partial reduce (16 chunks) + CAM softmax; att hi/lo bf16.
// ============================================================
__global__ void k_cam_softmax()
{
    __shared__ float buf[64];
    int rowid = blockIdx.x;
    int b = rowid >> 6, c = rowid & 63;
    int d = threadIdx.x;
    float v = 0.f;
#pragma unroll
    for (int ch = 0; ch < 16; ch++)
        v += g_attp[(ch * 8 + b) * 4096 + c * 64 + d];
    buf[d] = v;
    __syncthreads();
    for (int s = 32; s > 0; s >>= 1) {
        if (d < s) buf[d] = fminf(buf[d], buf[d + s]);
        __syncthreads();
    }
    float mn = buf[0];
    __syncthreads();
    float p = __expf(mn - v);
    buf[d] = p;
    __syncthreads();
    for (int s = 32; s > 0; s >>= 1) {
        if (d < s) buf[d] += buf[d + s];
        __syncthreads();
    }
    float a = p / buf[0];
    __nv_bfloat16 h = __float2bfloat16_rn(a);
    g_atth[rowid * 64 + d] = h;
    g_attl[rowid * 64 + d] = __float2bfloat16_rn(a - __bfloat162float(h));
}

// ============================================================
// Kernel 5: CAM apply via tensor cores (hi/lo split both operands).
// ============================================================
struct CamSmem {
    __align__(16) __nv_bfloat16 Ah[64][72];
    __align__(16) __nv_bfloat16 Al[64][72];
    __align__(16) __nv_bfloat16 Xh[64][136];
    __align__(16) __nv_bfloat16 Xl[64][136];
};

__global__ void __launch_bounds__(256) k_cam_apply_tc(const float* __restrict__ beta)
{
    __shared__ CamSmem sm;
    int b = blockIdx.y;
    int n0 = blockIdx.x * 128;
    int tid = threadIdx.x, warp = tid >> 5, lane = tid & 31;
    int wm = warp & 3, wn = warp >> 2;
    int row = lane >> 2, t2 = 2 * (lane & 3);

    unsigned int ahB = (unsigned int)__cvta_generic_to_shared(&sm.Ah[0][0]);
    unsigned int alB = (unsigned int)__cvta_generic_to_shared(&sm.Al[0][0]);
    unsigned int xhB = (unsigned int)__cvta_generic_to_shared(&sm.Xh[0][0]);
    unsigned int xlB = (unsigned int)__cvta_generic_to_shared(&sm.Xl[0][0]);

    for (int i = tid; i < 512; i += 256) {
        int c = i >> 3, seg = i & 7;
        cp16(ahB + (c * 72 + seg * 8) * 2, g_atth + b * 4096 + c * 64 + seg * 8);
        cp16(alB + (c * 72 + seg * 8) * 2, g_attl + b * 4096 + c * 64 + seg * 8);
    }
    for (int i = tid; i < 1024; i += 256) {
        int d = i >> 4, seg = i & 15;
        size_t src = (size_t)(b * 64 + d) * NN + n0 + seg * 8;
        cp16(xhB + (d * 136 + seg * 8) * 2, g_x1h + src);
        cp16(xlB + (d * 136 + seg * 8) * 2, g_x1l + src);
    }
    cp_commit();
    asm volatile("cp.async.wait_group 0;");
    __syncthreads();

    float acc[8][4];
#pragma unroll
    for (int i = 0; i < 8; i++)
#pragma unroll
        for (int j = 0; j < 4; j++) acc[i][j] = 0.f;

    int l15 = lane & 15;
#pragma unroll
    for (int ks = 0; ks < 4; ks++) {
        int d0 = ks * 16;
        unsigned int ah[4], al_[4];
        ah[0]  = *(const unsigned int*)&sm.Ah[wm * 16 + row][d0 + t2];
        ah[1]  = *(const unsigned int*)&sm.Ah[wm * 16 + row + 8][d0 + t2];
        ah[2]  = *(const unsigned int*)&sm.Ah[wm * 16 + row][d0 + t2 + 8];
        ah[3]  = *(const unsigned int*)&sm.Ah[wm * 16 + row + 8][d0 + t2 + 8];
        al_[0] = *(const unsigned int*)&sm.Al[wm * 16 + row][d0 + t2];
        al_[1] = *(const unsigned int*)&sm.Al[wm * 16 + row + 8][d0 + t2];
        al_[2] = *(const unsigned int*)&sm.Al[wm * 16 + row][d0 + t2 + 8];
        al_[3] = *(const unsigned int*)&sm.Al[wm * 16 + row + 8][d0 + t2 + 8];
#pragma unroll
        for (int nf = 0; nf < 8; nf++) {
            int nb = wn * 64 + nf * 8;
            unsigned int bh0, bh1, bl0, bl1;
            ldsm2t(bh0, bh1, xhB + ((d0 + l15) * 136 + nb) * 2);
            ldsm2t(bl0, bl1, xlB + ((d0 + l15) * 136 + nb) * 2);
            mma_pv(acc[nf], ah, bh0, bh1);
            mma_pv(acc[nf], ah, bl0, bl1);
            mma_pv(acc[nf], al_, bh0, bh1);
        }
    }

    float be = beta[0];
#pragma unroll
    for (int nf = 0; nf < 8; nf++) {
#pragma unroll
        for (int jh = 0; jh < 2; jh++) {
            int c = wm * 16 + row + jh * 8;
            int nl = wn * 64 + nf * 8 + t2;
            float2 xh = bfu2f(*(const unsigned int*)&sm.Xh[c][nl]);
            float2 xl = bfu2f(*(const unsigned int*)&sm.Xl[c][nl]);
            float2 o;
            o.x = __uint_as_float(tf32r(be * acc[nf][jh * 2]     + (xh.x + xl.x)));
            o.y = __uint_as_float(tf32r(be * acc[nf][jh * 2 + 1] + (xh.y + xl.y)));
            *(float2*)&g_x2[(size_t)(b * 64 + c) * NN + n0 + nl] = o;
        }
    }
}

// ============================================================
// Kernel 6: conv3x3 tf32 implicit GEMM + fused BN partial stats.
// ============================================================
struct ConvSmem {
    unsigned int Xs[32 * 296];
    unsigned int Ws[128 * 36];
};

__global__ void __launch_bounds__(256) k_conv_tc(const float* __restrict__ bias)
{
    __shared__ ConvSmem sm;
    __shared__ float bnS[8][32], bnQ[8][32];

    int y0 = blockIdx.x * 2, b = blockIdx.y;
    int tid = threadIdx.x, warp = tid >> 5, lane = tid & 31;
    int g = lane >> 2, t = lane & 3;
    int ocq = warp & 3, rowsel = warp >> 2;
    int mo = ocq * 32;

    float C[64];
#pragma unroll
    for (int i = 0; i < 64; i++) C[i] = 0.f;

    for (int ich = 0; ich < 2; ich++) {
        __syncthreads();
        for (int idx = tid; idx < 32 * 4 * 66; idx += 256) {
            int ic = idx / 264;
            int r = idx - ic * 264;
            int dy = r / 66, col = r - dy * 66;
            int ih = y0 + dy - 1, ix = col - 1;
            float v = 0.f;
            if (ih >= 0 && ih < 64 && ix >= 0 && ix < 64)
                v = g_x2[((b * 64 + ich * 32 + ic) * NN) + ih * 64 + ix];
            sm.Xs[ic * 296 + dy * 72 + col] = __float_as_uint(v);
        }
        for (int tap = 0; tap < 9; tap++) {
            __syncthreads();
            for (int idx = tid; idx < 4096; idx += 256) {
                int icrel = idx >> 7, oc = idx & 127;
                sm.Ws[oc * 36 + icrel] = g_wT[(tap * 64 + ich * 32 + icrel) * 128 + oc];
            }
            __syncthreads();
            int kh = tap / 3, kw = tap - kh * 3;
            int xoff = (rowsel + kh) * 72 + g + kw;
#pragma unroll
            for (int ks = 0; ks < 4; ks++) {
                int k8 = ks * 8;
                unsigned int a0 = sm.Ws[(mo + g) * 36 + k8 + t];
                unsigned int a1 = sm.Ws[(mo + g + 8) * 36 + k8 + t];
                unsigned int a2 = sm.Ws[(mo + g) * 36 + k8 + t + 4];
                unsigned int a3 = sm.Ws[(mo + g + 8) * 36 + k8 + t + 4];
                unsigned int a4 = sm.Ws[(mo + 16 + g) * 36 + k8 + t];
                unsigned int a5 = sm.Ws[(mo + 16 + g + 8) * 36 + k8 + t];
                unsigned int a6 = sm.Ws[(mo + 16 + g) * 36 + k8 + t + 4];
                unsigned int a7 = sm.Ws[(mo + 16 + g + 8) * 36 + k8 + t + 4];
#pragma unroll
                for (int nf = 0; nf < 8; nf++) {
                    unsigned int b0 = sm.Xs[(k8 + t) * 296 + xoff + nf * 8];
                    unsigned int b1 = sm.Xs[(k8 + t + 4) * 296 + xoff + nf * 8];
                    mma_tf32(&C[nf * 4], a0, a1, a2, a3, b0, b1);
                    mma_tf32(&C[32 + nf * 4], a4, a5, a6, a7, b0, b1);
                }
            }
        }
    }

    int oh = y0 + rowsel;
    float psum[2][2], psq[2][2];
#pragma unroll
    for (int mt = 0; mt < 2; mt++) {
        int oc0 = mo + mt * 16 + g, oc1 = oc0 + 8;
        float bs0 = bias[oc0], bs1 = bias[oc1];
        float* base0 = &g_conv[((b * OC + oc0) * NN) + oh * 64];
        float* base1 = &g_conv[((b * OC + oc1) * NN) + oh * 64];
        float s0 = 0.f, q0 = 0.f, s1 = 0.f, q1 = 0.f;
#pragma unroll
        for (int nf = 0; nf < 8; nf++) {
            int px = nf * 8 + 2 * t;
            float v0 = C[mt * 32 + nf * 4 + 0] + bs0;
            float v1 = C[mt * 32 + nf * 4 + 1] + bs0;
            float v2 = C[mt * 32 + nf * 4 + 2] + bs1;
            float v3 = C[mt * 32 + nf * 4 + 3] + bs1;
            *(float2*)&base0[px] = make_float2(v0, v1);
            *(float2*)&base1[px] = make_float2(v2, v3);
            s0 += v0 + v1; q0 += v0 * v0 + v1 * v1;
            s1 += v2 + v3; q1 += v2 * v2 + v3 * v3;
        }
        psum[mt][0] = s0; psq[mt][0] = q0;
        psum[mt][1] = s1; psq[mt][1] = q1;
    }
#pragma unroll
    for (int mt = 0; mt < 2; mt++)
#pragma unroll
        for (int p = 0; p < 2; p++) {
            psum[mt][p] += __shfl_xor_sync(0xffffffffu, psum[mt][p], 1);
            psum[mt][p] += __shfl_xor_sync(0xffffffffu, psum[mt][p], 2);
            psq[mt][p]  += __shfl_xor_sync(0xffffffffu, psq[mt][p], 1);
            psq[mt][p]  += __shfl_xor_sync(0xffffffffu, psq[mt][p], 2);
        }
    if (t == 0) {
#pragma unroll
        for (int mt = 0; mt < 2; mt++)
#pragma unroll
            for (int p = 0; p < 2; p++) {
                int li = mt * 16 + g + p * 8;
                bnS[warp][li] = psum[mt][p];
                bnQ[warp][li] = psq[mt][p];
            }
    }
    __syncthreads();
    {
        int which = tid >> 7, oc = tid & 127;
        int q = oc >> 5, li = oc & 31;
        float v = which ? (bnQ[q][li] + bnQ[q + 4][li])
                        : (bnS[q][li] + bnS[q + 4][li]);
        g_bnp[(b * 32 + blockIdx.x) * 256 + tid] = v;
    }
}

// ============================================================
// Kernel 7: BN stats (inline reduce) + BN + ReLU + maxpool
// ============================================================
__global__ void k_final(const float* __restrict__ gamma,
                        const float* __restrict__ betaBN,
                        float* __restrict__ out)
{
    __shared__ float s1[256], s2b[256];
    int bc = blockIdx.x;
    int b = bc >> 7, ch = bc & 127;
    int tid = threadIdx.x;

    s1[tid]  = g_bnp[tid * 256 + ch];
    s2b[tid] = g_bnp[tid * 256 + 128 + ch];
    __syncthreads();
    for (int st = 128; st > 0; st >>= 1) {
        if (tid < st) { s1[tid] += s1[tid + st]; s2b[tid] += s2b[tid + st]; }
        __syncthreads();
    }
    float mean = s1[0] * (1.f / 32768.f);
    float var = s2b[0] * (1.f / 32768.f) - mean * mean;
    float istd = rsqrtf(var + 1e-5f);

    float ga = gamma[ch], be = betaBN[ch];
    const float* src = &g_conv[(b * OC + ch) * NN];
    float* dst = &out[(b * OC + ch) * 33 * 32];
    for (int idx = tid; idx < 33 * 32; idx += 256) {
        int ohp = idx >> 5, ow = idx & 31;
        float m = 0.f;
        int ih0 = 2 * ohp - 1;
#pragma unroll
        for (int dy = 0; dy < 2; dy++) {
            int ih = ih0 + dy;
            if (ih < 0 || ih > 63) continue;
#pragma unroll
            for (int dx = 0; dx < 2; dx++) {
                float v = src[ih * 64 + 2 * ow + dx];
                v = (v - mean) * istd * ga + be;
                m = fmaxf(m, v);
            }
        }
        dst[ohp * 32 + ow] = m;
    }
}

// ============================================================
extern "C" void kernel_launch(void* const* d_in, const int* in_sizes, int n_in,
                              void* d_out, int out_size)
{
    const float* x      = (const float*)d_in[0];
    const float* wb     = (const float*)d_in[1];
    const float* bbv    = (const float*)d_in[2];
    const float* wc     = (const float*)d_in[3];
    const float* bcv    = (const float*)d_in[4];
    const float* wd     = (const float*)d_in[5];
    const float* bdv    = (const float*)d_in[6];
    const float* alpha  = (const float*)d_in[7];
    const float* beta   = (const float*)d_in[8];
    const float* convw  = (const float*)d_in[9];
    const float* convb  = (const float*)d_in[10];
    const float* gamma  = (const float*)d_in[11];
    const float* bnbeta = (const float*)d_in[12];
    float* out = (float*)d_out;

    k_wt<<<288, 256>>>(convw);
    k_proj<<<dim3(32, 8), 128>>>(x, wb, bbv, wc, bcv, wd, bdv);
    k_pam_tc<<<dim3(32, 8), 256>>>(x, alpha);
    k_gram_tc<<<dim3(16, 8), 256>>>();
    k_cam_softmax<<<512, 64>>>();
    k_cam_apply_tc<<<dim3(32, 8), 256>>>(beta);
    k_conv_tc<<<dim3(32, 8), 256>>>(convb);
    k_final<<<1024, 256>>>(gamma, bnbeta, out);
}

// round 17
// speedup vs baseline: 1.6433x; 1.0121x over previous
#include <cuda_runtime.h>
#include <cuda_bf16.h>

#define DEV __device__ __forceinline__

// ---- packed 2x fp32 helpers ----
DEV unsigned long long ffma2(unsigned long long a, unsigned long long b, unsigned long long c) {
    unsigned long long d;
    asm("fma.rn.f32x2 %0, %1, %2, %3;" : "=l"(d) : "l"(a), "l"(b), "l"(c));
    return d;
}
DEV unsigned long long pack2(float lo, float hi) {
    unsigned long long r;
    asm("mov.b64 %0, {%1,%2};" : "=l"(r) : "f"(lo), "f"(hi));
    return r;
}
DEV void unpack2(unsigned long long v, float& lo, float& hi) {
    asm("mov.b64 {%0,%1}, %2;" : "=f"(lo), "=f"(hi) : "l"(v));
}
DEV unsigned int bf2(float lo, float hi) {
    unsigned int r;
    asm("cvt.rn.bf16x2.f32 %0, %1, %2;" : "=r"(r) : "f"(hi), "f"(lo));
    return r;
}
DEV unsigned int tf32r(float f) {
    unsigned int r;
    asm("cvt.rna.tf32.f32 %0, %1;" : "=r"(r) : "f"(f));
    return r;
}
DEV float2 bfu2f(unsigned int u) {
    __nv_bfloat162 h = *(__nv_bfloat162*)&u;
    return make_float2(__bfloat162float(h.x), __bfloat162float(h.y));
}
// Schraudolph fast exp (~1.5% RMS, zero-mean)
DEV float fexp(float x) {
    float t = fmaf(x, 12102203.0f, 1064866805.0f);
    return __int_as_float(__float2int_rn(t));
}

DEV void mma_qk(float* d, const unsigned int* a, unsigned int b) {
    asm("mma.sync.aligned.m16n8k8.row.col.f32.bf16.bf16.f32 "
        "{%0,%1,%2,%3},{%4,%5},{%6},{%7,%7,%7,%7};"
        : "=f"(d[0]), "=f"(d[1]), "=f"(d[2]), "=f"(d[3])
        : "r"(a[0]), "r"(a[1]), "r"(b), "f"(0.f));
}
DEV void mma_pv(float* d, const unsigned int* a, unsigned int b0, unsigned int b1) {
    asm("mma.sync.aligned.m16n8k16.row.col.f32.bf16.bf16.f32 "
        "{%0,%1,%2,%3},{%4,%5,%6,%7},{%8,%9},{%0,%1,%2,%3};"
        : "+f"(d[0]), "+f"(d[1]), "+f"(d[2]), "+f"(d[3])
        : "r"(a[0]), "r"(a[1]), "r"(a[2]), "r"(a[3]), "r"(b0), "r"(b1));
}
DEV void mma_tf32(float* d, unsigned int a0, unsigned int a1, unsigned int a2, unsigned int a3,
                  unsigned int b0, unsigned int b1) {
    asm("mma.sync.aligned.m16n8k8.row.col.f32.tf32.tf32.f32 "
        "{%0,%1,%2,%3},{%4,%5,%6,%7},{%8,%9},{%0,%1,%2,%3};"
        : "+f"(d[0]), "+f"(d[1]), "+f"(d[2]), "+f"(d[3])
        : "r"(a0), "r"(a1), "r"(a2), "r"(a3), "r"(b0), "r"(b1));
}
DEV void ldsm2t(unsigned int& r0, unsigned int& r1, unsigned int addr) {
    asm volatile("ldmatrix.sync.aligned.m8n8.x2.trans.shared.b16 {%0,%1},[%2];"
                 : "=r"(r0), "=r"(r1) : "r"(addr));
}

DEV void cp16(unsigned int dst, const void* src) {
    asm volatile("cp.async.ca.shared.global [%0], [%1], 16;" :: "r"(dst), "l"(src));
}
DEV void cp_commit() { asm volatile("cp.async.commit_group;"); }

#define BB 8
#define CC 64
#define NN 4096
#define OC 128

// ---- scratch ----
__device__ float g_featb[BB * 8 * NN];
__device__ __align__(16) unsigned int   g_featcT[BB * NN * 4];   // [b][n][8 ch] bf16 packed
__device__ __align__(16) __nv_bfloat16  g_featd16[BB * CC * NN]; // [b][c][n] bf16
__device__ __align__(16) __nv_bfloat16 g_x1h[BB * CC * NN];      // hi bf16 of x1
__device__ __align__(16) __nv_bfloat16 g_x1l[BB * CC * NN];      // lo bf16 of x1
__device__ float g_x2[BB * CC * NN];                             // tf32-rounded
__device__ float g_attp[16 * BB * CC * CC];
__device__ __align__(16) __nv_bfloat16 g_atth[BB * CC * CC];
__device__ __align__(16) __nv_bfloat16 g_attl[BB * CC * CC];
__device__ float g_conv[BB * OC * NN];
__device__ float g_bnp[256 * 256];
__device__ unsigned int g_wT[9 * 64 * 128];   // tf32 weights [tap][ic][oc]

// ============================================================
// Kernel 1: fused 1x1 projections (f32x2), bf16 outputs for PAM.
// Also absorbs the one-time conv weight transpose (tf32 round).
// ============================================================
__global__ void __launch_bounds__(128) k_proj(
    const float* __restrict__ x,
    const float* __restrict__ wb, const float* __restrict__ bb,
    const float* __restrict__ wc, const float* __restrict__ bc,
    const float* __restrict__ wd, const float* __restrict__ bd,
    const float* __restrict__ convw)
{
    __shared__ __align__(16) float Ws[80 * 64];
    int b = blockIdx.y;
    int n = blockIdx.x * 128 + threadIdx.x;

    // fold: conv weight transpose + tf32 round (73728 elems / 32768 threads)
    {
        int flat = (b * 32 + blockIdx.x) * 128 + threadIdx.x;
        for (int idx = flat; idx < 9 * 64 * 128; idx += 32768) {
            int tap = idx >> 13;
            int r = idx & 8191;
            int ic = r >> 7, oc = r & 127;
            g_wT[idx] = tf32r(convw[(oc * 64 + ic) * 9 + tap]);
        }
    }

    for (int idx = threadIdx.x; idx < 80 * 64; idx += 128) {
        float v;
        if (idx < 512)       v = wb[idx];
        else if (idx < 1024) v = wc[idx - 512];
        else                 v = wd[idx - 1024];
        Ws[idx] = v;
    }
    __syncthreads();

    unsigned long long xv2[32];
#pragma unroll
    for (int j = 0; j < 32; j++)
        xv2[j] = pack2(x[(b * 64 + 2 * j) * NN + n], x[(b * 64 + 2 * j + 1) * NN + n]);

    const unsigned long long* Ws2 = (const unsigned long long*)Ws;

#pragma unroll
    for (int o = 0; o < 8; o++) {
        unsigned long long s2 = 0ull;
        const unsigned long long* w = &Ws2[o * 32];
#pragma unroll
        for (int j = 0; j < 32; j++) s2 = ffma2(w[j], xv2[j], s2);
        float lo, hi; unpack2(s2, lo, hi);
        g_featb[(b * 8 + o) * NN + n] = bb[o] + lo + hi;
    }
    {
        float fc[8];
#pragma unroll
        for (int o = 0; o < 8; o++) {
            unsigned long long s2 = 0ull;
            const unsigned long long* w = &Ws2[256 + o * 32];
#pragma unroll
            for (int j = 0; j < 32; j++) s2 = ffma2(w[j], xv2[j], s2);
            float lo, hi; unpack2(s2, lo, hi);
            fc[o] = bc[o] + lo + hi;
        }
        uint4 p;
        p.x = bf2(fc[0], fc[1]); p.y = bf2(fc[2], fc[3]);
        p.z = bf2(fc[4], fc[5]); p.w = bf2(fc[6], fc[7]);
        ((uint4*)g_featcT)[b * NN + n] = p;
    }
    for (int o = 0; o < 64; o++) {
        unsigned long long s2 = 0ull;
        const unsigned long long* w = &Ws2[512 + o * 32];
#pragma unroll
        for (int j = 0; j < 32; j++) s2 = ffma2(w[j], xv2[j], s2);
        float lo, hi; unpack2(s2, lo, hi);
        g_featd16[(b * 64 + o) * NN + n] = __float2bfloat16_rn(bd[o] + lo + hi);
    }
}

// ============================================================
// Kernel 2: PAM flash attention (bf16 mma + cp.async double buffer).
// Schraudolph exp; R8 epilogue (proven no-spill).
// ============================================================
struct PamSmem {
    __align__(16) __nv_bfloat16 Ks[2][128][8];
    __align__(16) unsigned int Vs[2][64][68];
};

__global__ void __launch_bounds__(256, 2) k_pam_tc(
    const float* __restrict__ x, const float* __restrict__ alpha)
{
    __shared__ PamSmem sm;

    int b = blockIdx.y, qt = blockIdx.x;
    int tid = threadIdx.x, warp = tid >> 5, lane = tid & 31;
    int n0 = qt * 128;
    int row = warp * 16 + (lane >> 2);
    int qc = 2 * (lane & 3);

    const float* fb = g_featb + b * 8 * NN;
    unsigned int qa[2];
    qa[0] = bf2(fb[qc * NN + n0 + row],     fb[(qc + 1) * NN + n0 + row]);
    qa[1] = bf2(fb[qc * NN + n0 + row + 8], fb[(qc + 1) * NN + n0 + row + 8]);

    float Oacc[32];
#pragma unroll
    for (int i = 0; i < 32; i++) Oacc[i] = 0.f;
    float ssum0 = 0.f, ssum1 = 0.f;

    const __nv_bfloat16* fcT = (const __nv_bfloat16*)g_featcT + (size_t)b * NN * 8;
    const __nv_bfloat16* fd  = g_featd16 + (size_t)b * 64 * NN;

    unsigned int ksBase = (unsigned int)__cvta_generic_to_shared(&sm.Ks[0][0][0]);
    unsigned int vsBase = (unsigned int)__cvta_generic_to_shared(&sm.Vs[0][0][0]);

    auto stage = [&](int buf, int m0) {
        if (tid < 128)
            cp16(ksBase + (buf * 128 + tid) * 16, fcT + (size_t)(m0 + tid) * 8);
#pragma unroll
        for (int j = 0; j < 4; j++) {
            int id = tid + 256 * j;
            int c = id >> 4, ch = id & 15;
            cp16(vsBase + (buf * 64 * 68 + c * 68 + ch * 4) * 4,
                 fd + (size_t)c * NN + m0 + ch * 8);
        }
    };

    stage(0, 0);
    cp_commit();

    for (int tt = 0; tt < 32; tt++) {
        int cur = tt & 1;
        if (tt < 31) {
            stage(cur ^ 1, (tt + 1) * 128);
            cp_commit();
            asm volatile("cp.async.wait_group 1;");
        } else {
            asm volatile("cp.async.wait_group 0;");
        }
        __syncthreads();

#pragma unroll
        for (int half = 0; half < 2; half++) {
            float Cf[8][4];
#pragma unroll
            for (int nt = 0; nt < 8; nt++) {
                unsigned int kb = *(const unsigned int*)&sm.Ks[cur][half * 64 + nt * 8 + (lane >> 2)][qc];
                mma_qk(Cf[nt], qa, kb);
            }
            unsigned int pa[4][4];
#pragma unroll
            for (int kt = 0; kt < 4; kt++) {
                float ea0 = fexp(Cf[2 * kt][0]),     ea1 = fexp(Cf[2 * kt][1]);
                float ea2 = fexp(Cf[2 * kt][2]),     ea3 = fexp(Cf[2 * kt][3]);
                float eb0 = fexp(Cf[2 * kt + 1][0]), eb1 = fexp(Cf[2 * kt + 1][1]);
                float eb2 = fexp(Cf[2 * kt + 1][2]), eb3 = fexp(Cf[2 * kt + 1][3]);
                ssum0 += (ea0 + ea1) + (eb0 + eb1);
                ssum1 += (ea2 + ea3) + (eb2 + eb3);
                pa[kt][0] = bf2(ea0, ea1);
                pa[kt][1] = bf2(ea2, ea3);
                pa[kt][2] = bf2(eb0, eb1);
                pa[kt][3] = bf2(eb2, eb3);
            }
#pragma unroll
            for (int kt = 0; kt < 4; kt++) {
                int kw = (half * 64 + kt * 16 + 2 * (lane & 3)) >> 1;
#pragma unroll
                for (int nt = 0; nt < 8; nt++) {
                    int c = nt * 8 + (lane >> 2);
                    unsigned int b0 = sm.Vs[cur][c][kw];
                    unsigned int b1 = sm.Vs[cur][c][kw + 4];
                    mma_pv(&Oacc[nt * 4], pa[kt], b0, b1);
                }
            }
        }
        __syncthreads();
    }

    ssum0 += __shfl_xor_sync(0xffffffffu, ssum0, 1);
    ssum0 += __shfl_xor_sync(0xffffffffu, ssum0, 2);
    ssum1 += __shfl_xor_sync(0xffffffffu, ssum1, 1);
    ssum1 += __shfl_xor_sync(0xffffffffu, ssum1, 2);
    float inv0 = __fdividef(1.f, ssum0);
    float inv1 = __fdividef(1.f, ssum1);

    float al = alpha[0];
#pragma unroll
    for (int nt = 0; nt < 8; nt++) {
#pragma unroll
        for (int j = 0; j < 4; j++) {
            int r = row + ((j >= 2) ? 8 : 0);
            int c = nt * 8 + qc + (j & 1);
            int n = n0 + r;
            float o = Oacc[nt * 4 + j] * ((j >= 2) ? inv1 : inv0);
            float v = al * o + x[(b * 64 + c) * NN + n];
            size_t off = (size_t)(b * 64 + c) * NN + n;
            __nv_bfloat16 h = __float2bfloat16_rn(v);
            g_x1h[off] = h;
            g_x1l[off] = __float2bfloat16_rn(v - __bfloat162float(h));
        }
    }
}

// ============================================================
// Kernel 3: CAM gram via bf16 hi/lo split tensor cores.
// ============================================================
struct GramSmem {
    __align__(16) __nv_bfloat16 H[64][264];
    __align__(16) __nv_bfloat16 L[64][264];
};

__global__ void __launch_bounds__(256) k_gram_tc()
{
    __shared__ GramSmem sm;
    int ck = blockIdx.x, b = blockIdx.y;
    int tid = threadIdx.x, warp = tid >> 5, lane = tid & 31;
    int n0 = ck * 256;

    unsigned int hBase = (unsigned int)__cvta_generic_to_shared(&sm.H[0][0]);
    unsigned int lBase = (unsigned int)__cvta_generic_to_shared(&sm.L[0][0]);
    for (int i = tid; i < 2048; i += 256) {
        int c = i >> 5, seg = i & 31;
        size_t src = (size_t)(b * 64 + c) * NN + n0 + seg * 8;
        cp16(hBase + (c * 264 + seg * 8) * 2, g_x1h + src);
        cp16(lBase + (c * 264 + seg * 8) * 2, g_x1l + src);
    }
    cp_commit();
    asm volatile("cp.async.wait_group 0;");
    __syncthreads();

    int wr = (warp & 3) * 16;
    int wc = (warp >> 2) * 32;
    int row = lane >> 2, t2 = 2 * (lane & 3);

    float acc[4][4];
#pragma unroll
    for (int i = 0; i < 4; i++)
#pragma unroll
        for (int j = 0; j < 4; j++) acc[i][j] = 0.f;

#pragma unroll 4
    for (int ks = 0; ks < 16; ks++) {
        int k0 = ks * 16;
        unsigned int ah[4], al_[4];
        ah[0]  = *(const unsigned int*)&sm.H[wr + row][k0 + t2];
        ah[1]  = *(const unsigned int*)&sm.H[wr + row + 8][k0 + t2];
        ah[2]  = *(const unsigned int*)&sm.H[wr + row][k0 + t2 + 8];
        ah[3]  = *(const unsigned int*)&sm.H[wr + row + 8][k0 + t2 + 8];
        al_[0] = *(const unsigned int*)&sm.L[wr + row][k0 + t2];
        al_[1] = *(const unsigned int*)&sm.L[wr + row + 8][k0 + t2];
        al_[2] = *(const unsigned int*)&sm.L[wr + row][k0 + t2 + 8];
        al_[3] = *(const unsigned int*)&sm.L[wr + row + 8][k0 + t2 + 8];
#pragma unroll
        for (int nt = 0; nt < 4; nt++) {
            int col = wc + nt * 8 + row;
            unsigned int bh0 = *(const unsigned int*)&sm.H[col][k0 + t2];
            unsigned int bh1 = *(const unsigned int*)&sm.H[col][k0 + t2 + 8];
            unsigned int bl0 = *(const unsigned int*)&sm.L[col][k0 + t2];
            unsigned int bl1 = *(const unsigned int*)&sm.L[col][k0 + t2 + 8];
            mma_pv(acc[nt], ah, bh0, bh1);
            mma_pv(acc[nt], ah, bl0, bl1);
            mma_pv(acc[nt], al_, bh0, bh1);
        }
    }

    float* outp = &g_attp[(ck * 8 + b) * 4096];
#pragma unroll
    for (int nt = 0; nt < 4; nt++)
#pragma unroll
        for (int j = 0; j < 4; j++) {
            int c = wr + row + ((j >= 2) ? 8 : 0);
            int d = wc + nt * 8 + t2 + (j & 1);
            outp[c * 64 + d] = acc[nt][j];
        }
}

// ============================================================
// Kernel 4: partial reduce (16 chunks) + CAM softmax; att hi/lo bf16.
// 4 rows per 256-thread block (grid 128).
// ============================================================
__global__ void __launch_bounds__(256) k_cam_softmax()
{
    __shared__ float buf[256];
    int tid = threadIdx.x;
    int rowid = blockIdx.x * 4 + (tid >> 6);
    int b = rowid >> 6, c = rowid & 63;
    int d = tid & 63;
    int seg = tid & ~63;

    float v = 0.f;
#pragma unroll
    for (int ch = 0; ch < 16; ch++)
        v += g_attp[(ch * 8 + b) * 4096 + c * 64 + d];
    buf[tid] = v;
    __syncthreads();
    for (int s = 32; s > 0; s >>= 1) {
        if (d < s) buf[tid] = fminf(buf[tid], buf[tid + s]);
        __syncthreads();
    }
    float mn = buf[seg];
    __syncthreads();
    float p = __expf(mn - v);
    buf[tid] = p;
    __syncthreads();
    for (int s = 32; s > 0; s >>= 1) {
        if (d < s) buf[tid] += buf[tid + s];
        __syncthreads();
    }
    float a = p / buf[seg];
    __nv_bfloat16 h = __float2bfloat16_rn(a);
    g_atth[rowid * 64 + d] = h;
    g_attl[rowid * 64 + d] = __float2bfloat16_rn(a - __bfloat162float(h));
}

// ============================================================
// Kernel 5: CAM apply via tensor cores (hi/lo split both operands).
// x2 emitted pre-rounded to tf32 (sole consumer is the tf32 conv).
// ============================================================
struct CamSmem {
    __align__(16) __nv_bfloat16 Ah[64][72];
    __align__(16) __nv_bfloat16 Al[64][72];
    __align__(16) __nv_bfloat16 Xh[64][136];
    __align__(16) __nv_bfloat16 Xl[64][136];
};

__global__ void __launch_bounds__(256) k_cam_apply_tc(const float* __restrict__ beta)
{
    __shared__ CamSmem sm;
    int b = blockIdx.y;
    int n0 = blockIdx.x * 128;
    int tid = threadIdx.x, warp = tid >> 5, lane = tid & 31;
    int wm = warp & 3, wn = warp >> 2;
    int row = lane >> 2, t2 = 2 * (lane & 3);

    unsigned int ahB = (unsigned int)__cvta_generic_to_shared(&sm.Ah[0][0]);
    unsigned int alB = (unsigned int)__cvta_generic_to_shared(&sm.Al[0][0]);
    unsigned int xhB = (unsigned int)__cvta_generic_to_shared(&sm.Xh[0][0]);
    unsigned int xlB = (unsigned int)__cvta_generic_to_shared(&sm.Xl[0][0]);

    for (int i = tid; i < 512; i += 256) {
        int c = i >> 3, seg = i & 7;
        cp16(ahB + (c * 72 + seg * 8) * 2, g_atth + b * 4096 + c * 64 + seg * 8);
        cp16(alB + (c * 72 + seg * 8) * 2, g_attl + b * 4096 + c * 64 + seg * 8);
    }
    for (int i = tid; i < 1024; i += 256) {
        int d = i >> 4, seg = i & 15;
        size_t src = (size_t)(b * 64 + d) * NN + n0 + seg * 8;
        cp16(xhB + (d * 136 + seg * 8) * 2, g_x1h + src);
        cp16(xlB + (d * 136 + seg * 8) * 2, g_x1l + src);
    }
    cp_commit();
    asm volatile("cp.async.wait_group 0;");
    __syncthreads();

    float acc[8][4];
#pragma unroll
    for (int i = 0; i < 8; i++)
#pragma unroll
        for (int j = 0; j < 4; j++) acc[i][j] = 0.f;

    int l15 = lane & 15;
#pragma unroll
    for (int ks = 0; ks < 4; ks++) {
        int d0 = ks * 16;
        unsigned int ah[4], al_[4];
        ah[0]  = *(const unsigned int*)&sm.Ah[wm * 16 + row][d0 + t2];
        ah[1]  = *(const unsigned int*)&sm.Ah[wm * 16 + row + 8][d0 + t2];
        ah[2]  = *(const unsigned int*)&sm.Ah[wm * 16 + row][d0 + t2 + 8];
        ah[3]  = *(const unsigned int*)&sm.Ah[wm * 16 + row + 8][d0 + t2 + 8];
        al_[0] = *(const unsigned int*)&sm.Al[wm * 16 + row][d0 + t2];
        al_[1] = *(const unsigned int*)&sm.Al[wm * 16 + row + 8][d0 + t2];
        al_[2] = *(const unsigned int*)&sm.Al[wm * 16 + row][d0 + t2 + 8];
        al_[3] = *(const unsigned int*)&sm.Al[wm * 16 + row + 8][d0 + t2 + 8];
#pragma unroll
        for (int nf = 0; nf < 8; nf++) {
            int nb = wn * 64 + nf * 8;
            unsigned int bh0, bh1, bl0, bl1;
            ldsm2t(bh0, bh1, xhB + ((d0 + l15) * 136 + nb) * 2);
            ldsm2t(bl0, bl1, xlB + ((d0 + l15) * 136 + nb) * 2);
            mma_pv(acc[nf], ah, bh0, bh1);
            mma_pv(acc[nf], ah, bl0, bl1);
            mma_pv(acc[nf], al_, bh0, bh1);
        }
    }

    float be = beta[0];
#pragma unroll
    for (int nf = 0; nf < 8; nf++) {
#pragma unroll
        for (int jh = 0; jh < 2; jh++) {
            int c = wm * 16 + row + jh * 8;
            int nl = wn * 64 + nf * 8 + t2;
            float2 xh = bfu2f(*(const unsigned int*)&sm.Xh[c][nl]);
            float2 xl = bfu2f(*(const unsigned int*)&sm.Xl[c][nl]);
            float2 o;
            o.x = __uint_as_float(tf32r(be * acc[nf][jh * 2]     + (xh.x + xl.x)));
            o.y = __uint_as_float(tf32r(be * acc[nf][jh * 2 + 1] + (xh.y + xl.y)));
            *(float2*)&g_x2[(size_t)(b * 64 + c) * NN + n0 + nl] = o;
        }
    }
}

// ============================================================
// Kernel 6: conv3x3 tf32 implicit GEMM + fused BN partial stats.
// ============================================================
struct ConvSmem {
    unsigned int Xs[32 * 296];
    unsigned int Ws[128 * 36];
};

__global__ void __launch_bounds__(256) k_conv_tc(const float* __restrict__ bias)
{
    __shared__ ConvSmem sm;
    __shared__ float bnS[8][32], bnQ[8][32];

    int y0 = blockIdx.x * 2, b = blockIdx.y;
    int tid = threadIdx.x, warp = tid >> 5, lane = tid & 31;
    int g = lane >> 2, t = lane & 3;
    int ocq = warp & 3, rowsel = warp >> 2;
    int mo = ocq * 32;

    float C[64];
#pragma unroll
    for (int i = 0; i < 64; i++) C[i] = 0.f;

    for (int ich = 0; ich < 2; ich++) {
        __syncthreads();
        for (int idx = tid; idx < 32 * 4 * 66; idx += 256) {
            int ic = idx / 264;
            int r = idx - ic * 264;
            int dy = r / 66, col = r - dy * 66;
            int ih = y0 + dy - 1, ix = col - 1;
            float v = 0.f;
            if (ih >= 0 && ih < 64 && ix >= 0 && ix < 64)
                v = g_x2[((b * 64 + ich * 32 + ic) * NN) + ih * 64 + ix];
            sm.Xs[ic * 296 + dy * 72 + col] = __float_as_uint(v);
        }
        for (int tap = 0; tap < 9; tap++) {
            __syncthreads();
            for (int idx = tid; idx < 4096; idx += 256) {
                int icrel = idx >> 7, oc = idx & 127;
                sm.Ws[oc * 36 + icrel] = g_wT[(tap * 64 + ich * 32 + icrel) * 128 + oc];
            }
            __syncthreads();
            int kh = tap / 3, kw = tap - kh * 3;
            int xoff = (rowsel + kh) * 72 + g + kw;
#pragma unroll
            for (int ks = 0; ks < 4; ks++) {
                int k8 = ks * 8;
                unsigned int a0 = sm.Ws[(mo + g) * 36 + k8 + t];
                unsigned int a1 = sm.Ws[(mo + g + 8) * 36 + k8 + t];
                unsigned int a2 = sm.Ws[(mo + g) * 36 + k8 + t + 4];
                unsigned int a3 = sm.Ws[(mo + g + 8) * 36 + k8 + t + 4];
                unsigned int a4 = sm.Ws[(mo + 16 + g) * 36 + k8 + t];
                unsigned int a5 = sm.Ws[(mo + 16 + g + 8) * 36 + k8 + t];
                unsigned int a6 = sm.Ws[(mo + 16 + g) * 36 + k8 + t + 4];
                unsigned int a7 = sm.Ws[(mo + 16 + g + 8) * 36 + k8 + t + 4];
#pragma unroll
                for (int nf = 0; nf < 8; nf++) {
                    unsigned int b0 = sm.Xs[(k8 + t) * 296 + xoff + nf * 8];
                    unsigned int b1 = sm.Xs[(k8 + t + 4) * 296 + xoff + nf * 8];
                    mma_tf32(&C[nf * 4], a0, a1, a2, a3, b0, b1);
                    mma_tf32(&C[32 + nf * 4], a4, a5, a6, a7, b0, b1);
                }
            }
        }
    }

    int oh = y0 + rowsel;
    float psum[2][2], psq[2][2];
#pragma unroll
    for (int mt = 0; mt < 2; mt++) {
        int oc0 = mo + mt * 16 + g, oc1 = oc0 + 8;
        float bs0 = bias[oc0], bs1 = bias[oc1];
        float* base0 = &g_conv[((b * OC + oc0) * NN) + oh * 64];
        float* base1 = &g_conv[((b * OC + oc1) * NN) + oh * 64];
        float s0 = 0.f, q0 = 0.f, s1 = 0.f, q1 = 0.f;
#pragma unroll
        for (int nf = 0; nf < 8; nf++) {
            int px = nf * 8 + 2 * t;
            float v0 = C[mt * 32 + nf * 4 + 0] + bs0;
            float v1 = C[mt * 32 + nf * 4 + 1] + bs0;
            float v2 = C[mt * 32 + nf * 4 + 2] + bs1;
            float v3 = C[mt * 32 + nf * 4 + 3] + bs1;
            *(float2*)&base0[px] = make_float2(v0, v1);
            *(float2*)&base1[px] = make_float2(v2, v3);
            s0 += v0 + v1; q0 += v0 * v0 + v1 * v1;
            s1 += v2 + v3; q1 += v2 * v2 + v3 * v3;
        }
        psum[mt][0] = s0; psq[mt][0] = q0;
        psum[mt][1] = s1; psq[mt][1] = q1;
    }
#pragma unroll
    for (int mt = 0; mt < 2; mt++)
#pragma unroll
        for (int p = 0; p < 2; p++) {
            psum[mt][p] += __shfl_xor_sync(0xffffffffu, psum[mt][p], 1);
            psum[mt][p] += __shfl_xor_sync(0xffffffffu, psum[mt][p], 2);
            psq[mt][p]  += __shfl_xor_sync(0xffffffffu, psq[mt][p], 1);
            psq[mt][p]  += __shfl_xor_sync(0xffffffffu, psq[mt][p], 2);
        }
    if (t == 0) {
#pragma unroll
        for (int mt = 0; mt < 2; mt++)
#pragma unroll
            for (int p = 0; p < 2; p++) {
                int li = mt * 16 + g + p * 8;
                bnS[warp][li] = psum[mt][p];
                bnQ[warp][li] = psq[mt][p];
            }
    }
    __syncthreads();
    {
        int which = tid >> 7, oc = tid & 127;
        int q = oc >> 5, li = oc & 31;
        float v = which ? (bnQ[q][li] + bnQ[q + 4][li])
                        : (bnS[q][li] + bnS[q + 4][li]);
        g_bnp[(b * 32 + blockIdx.x) * 256 + tid] = v;
    }
}

// ============================================================
// Kernel 7: BN stats (inline reduce) + BN + ReLU + maxpool
// ============================================================
__global__ void k_final(const float* __restrict__ gamma,
                        const float* __restrict__ betaBN,
                        float* __restrict__ out)
{
    __shared__ float s1[256], s2b[256];
    int bc = blockIdx.x;
    int b = bc >> 7, ch = bc & 127;
    int tid = threadIdx.x;

    s1[tid]  = g_bnp[tid * 256 + ch];
    s2b[tid] = g_bnp[tid * 256 + 128 + ch];
    __syncthreads();
    for (int st = 128; st > 0; st >>= 1) {
        if (tid < st) { s1[tid] += s1[tid + st]; s2b[tid] += s2b[tid + st]; }
        __syncthreads();
    }
    float mean = s1[0] * (1.f / 32768.f);
    float var = s2b[0] * (1.f / 32768.f) - mean * mean;
    float istd = rsqrtf(var + 1e-5f);

    float ga = gamma[ch], be = betaBN[ch];
    const float* src = &g_conv[(b * OC + ch) * NN];
    float* dst = &out[(b * OC + ch) * 33 * 32];
    for (int idx = tid; idx < 33 * 32; idx += 256) {
        int ohp = idx >> 5, ow = idx & 31;
        float m = 0.f;
        int ih0 = 2 * ohp - 1;
#pragma unroll
        for (int dy = 0; dy < 2; dy++) {
            int ih = ih0 + dy;
            if (ih < 0 || ih > 63) continue;
#pragma unroll
            for (int dx = 0; dx < 2; dx++) {
                float v = src[ih * 64 + 2 * ow + dx];
                v = (v - mean) * istd * ga + be;
                m = fmaxf(m, v);
            }
        }
        dst[ohp * 32 + ow] = m;
    }
}

// ============================================================
extern "C" void kernel_launch(void* const* d_in, const int* in_sizes, int n_in,
                              void* d_out, int out_size)
{
    const float* x      = (const float*)d_in[0];
    const float* wb     = (const float*)d_in[1];
    const float* bbv    = (const float*)d_in[2];
    const float* wc     = (const float*)d_in[3];
    const float* bcv    = (const float*)d_in[4];
    const float* wd     = (const float*)d_in[5];
    const float* bdv    = (const float*)d_in[6];
    const float* alpha  = (const float*)d_in[7];
    const float* beta   = (const float*)d_in[8];
    const float* convw  = (const float*)d_in[9];
    const float* convb  = (const float*)d_in[10];
    const float* gamma  = (const float*)d_in[11];
    const float* bnbeta = (const float*)d_in[12];
    float* out = (float*)d_out;

    k_proj<<<dim3(32, 8), 128>>>(x, wb, bbv, wc, bcv, wd, bdv, convw);
    k_pam_tc<<<dim3(32, 8), 256>>>(x, alpha);
    k_gram_tc<<<dim3(16, 8), 256>>>();
    k_cam_softmax<<<128, 256>>>();
    k_cam_apply_tc<<<dim3(32, 8), 256>>>(beta);
    k_conv_tc<<<dim3(32, 8), 256>>>(convb);
    k_final<<<1024, 256>>>(gamma, bnbeta, out);
}